// round 3
// baseline (speedup 1.0000x reference)
#include <cuda_runtime.h>
#include <cuda_bf16.h>
#include <math.h>

#define NN 50000
#define EE 800000
#define EMB 64
#define HID 128

typedef unsigned long long ull;

// ---------------- scratch (device globals; no allocation allowed) ----------------
__device__ float g_deg[NN];
__device__ float g_dinv[NN];
__device__ int   g_cnt[NN];
__device__ int   g_off[NN + 1];
__device__ int   g_cur[NN];
__device__ int   g_srcs[EE];
__device__ float g_wsrt[EE];

__device__ float g_z[NN * EMB];       // state z
__device__ float g_h[NN * HID];       // tag output (relu'd) / scratch
__device__ float g_b0[NN * HID];      // hop ping
__device__ float g_b1[NN * HID];      // hop pong
__device__ float g_acc[NN * HID];     // gemm accumulator
__device__ float g_y3[NN * EMB];      // tag3 scratch
__device__ float g_pp1[NN * 3];       // P pos
__device__ float g_pp2[NN * 3];       // P^2 pos
__device__ float g_pp3[NN * 3];       // P^3 pos
__device__ float g_posacc[NN * HID];  // sum_k (P^k pos) @ W1_k[64:67,:]

__device__ __forceinline__ float gelu_exact(float x) {
    return 0.5f * x * (1.0f + erff(x * 0.70710678118654752f));
}

__device__ __forceinline__ ull ffma2(ull a, ull b, ull c) {
    ull d;
    asm("fma.rn.f32x2 %0, %1, %2, %3;" : "=l"(d) : "l"(a), "l"(b), "l"(c));
    return d;
}
__device__ __forceinline__ ull pack2(float x, float y) {
    ull r;
    asm("mov.b64 %0, {%1, %2};" : "=l"(r) : "f"(x), "f"(y));
    return r;
}
__device__ __forceinline__ void unpack2(ull v, float& lo, float& hi) {
    asm("mov.b64 {%0, %1}, %2;" : "=f"(lo), "=f"(hi) : "l"(v));
}

// ---------------- setup kernels ----------------
__global__ void k_zero() {
    int i = blockIdx.x * blockDim.x + threadIdx.x;
    if (i < NN) { g_deg[i] = 0.f; g_cnt[i] = 0; }
}

__global__ void k_hist(const int* __restrict__ col, const float* __restrict__ ea) {
    int e = blockIdx.x * blockDim.x + threadIdx.x;
    if (e < EE) {
        int c = col[e];
        atomicAdd(&g_deg[c], ea[e]);
        atomicAdd(&g_cnt[c], 1);
    }
}

__global__ void k_dinv() {
    int i = blockIdx.x * blockDim.x + threadIdx.x;
    if (i < NN) {
        float d = g_deg[i];
        g_dinv[i] = (d > 0.f) ? rsqrtf(d) : 0.f;
    }
}

__global__ void k_scan() {
    __shared__ int sh[1024];
    int tid = threadIdx.x;
    int carry = 0;
    for (int base = 0; base < NN; base += 1024) {
        int i = base + tid;
        int v = (i < NN) ? g_cnt[i] : 0;
        sh[tid] = v;
        __syncthreads();
        for (int ofs = 1; ofs < 1024; ofs <<= 1) {
            int t = (tid >= ofs) ? sh[tid - ofs] : 0;
            __syncthreads();
            sh[tid] += t;
            __syncthreads();
        }
        if (i < NN) g_off[i] = carry + sh[tid] - v;
        carry += sh[1023];
        __syncthreads();
    }
    if (tid == 0) g_off[NN] = carry;
}

__global__ void k_cursor() {
    int i = blockIdx.x * blockDim.x + threadIdx.x;
    if (i < NN) g_cur[i] = g_off[i];
}

__global__ void k_scatter(const int* __restrict__ row, const int* __restrict__ col,
                          const float* __restrict__ ea) {
    int e = blockIdx.x * blockDim.x + threadIdx.x;
    if (e < EE) {
        int r = row[e], c = col[e];
        int p = atomicAdd(&g_cur[c], 1);
        g_srcs[p] = r;
        g_wsrt[p] = g_dinv[r] * ea[e] * g_dinv[c];
    }
}

// ---------------- pos hops (3 channels, thread per node) ----------------
__global__ void k_prop3(float* __restrict__ dst, const float* __restrict__ src) {
    int j = blockIdx.x * blockDim.x + threadIdx.x;
    if (j >= NN) return;
    int beg = g_off[j], end = g_off[j + 1];
    float a0 = 0.f, a1 = 0.f, a2 = 0.f;
    for (int e = beg; e < end; e++) {
        int s = g_srcs[e];
        float w = g_wsrt[e];
        a0 += w * src[s * 3 + 0];
        a1 += w * src[s * 3 + 1];
        a2 += w * src[s * 3 + 2];
    }
    dst[j * 3 + 0] = a0; dst[j * 3 + 1] = a1; dst[j * 3 + 2] = a2;
}

// posacc[n,c] = sum_{k=0..3} sum_{j=0..2} ppk[n,j] * c1_w[k][64+j][c]
__global__ void k_posacc(const float* __restrict__ pos, const float* __restrict__ c1w) {
    int idx = blockIdx.x * blockDim.x + threadIdx.x;
    if (idx >= NN * HID) return;
    int n = idx >> 7, c = idx & 127;
    const float* pps[4] = {pos, g_pp1, g_pp2, g_pp3};
    float acc = 0.f;
#pragma unroll
    for (int k = 0; k < 4; k++) {
        const float* pp = pps[k] + n * 3;
        const float* wr = c1w + k * 67 * 128 + 64 * 128 + c;
        acc += pp[0] * wr[0] + pp[1] * wr[128] + pp[2] * wr[256];
    }
    g_posacc[idx] = acc;
}

// ---------------- up MLP: z0 = gelu(x@W1+b1)@W2+b2 ----------------
__global__ __launch_bounds__(256) void k_up(const float* __restrict__ x,
                                            const float* __restrict__ w1, const float* __restrict__ b1,
                                            const float* __restrict__ w2, const float* __restrict__ b2) {
    __shared__ float sw2[64 * 64];
    __shared__ float hid[4][64];
    int tid = threadIdx.x;
#pragma unroll
    for (int i = 0; i < 16; i++) sw2[tid * 16 + i] = w2[tid * 16 + i];
    int local = tid >> 6;
    int c = tid & 63;
    int node = blockIdx.x * 4 + local;
    float h = 0.f;
    if (node < NN) {
        h = b1[c];
#pragma unroll
        for (int i = 0; i < 4; i++) h += x[node * 4 + i] * w1[i * 64 + c];
        h = gelu_exact(h);
    }
    hid[local][c] = h;
    __syncthreads();
    if (node < NN) {
        float o = b2[c];
#pragma unroll
        for (int j = 0; j < 64; j++) o += hid[local][j] * sw2[j * 64 + c];
        g_z[node * 64 + c] = o;
    }
}

// ---------------- propagation kernels (CSR, warp per node) ----------------
__global__ __launch_bounds__(256) void k_prop64(float* __restrict__ dst, const float* __restrict__ src) {
    int wrp = threadIdx.x >> 5, lane = threadIdx.x & 31;
    int j = blockIdx.x * 8 + wrp;
    if (j >= NN) return;
    int beg = g_off[j], end = g_off[j + 1];
    float2 a0 = {0.f, 0.f}, a1 = {0.f, 0.f};
    int e = beg;
    for (; e + 2 <= end; e += 2) {
        int s0 = g_srcs[e], s1 = g_srcs[e + 1];
        float w0 = g_wsrt[e], w1 = g_wsrt[e + 1];
        float2 v0 = *(const float2*)(src + (size_t)s0 * 64 + lane * 2);
        float2 v1 = *(const float2*)(src + (size_t)s1 * 64 + lane * 2);
        a0.x = fmaf(w0, v0.x, a0.x); a0.y = fmaf(w0, v0.y, a0.y);
        a1.x = fmaf(w1, v1.x, a1.x); a1.y = fmaf(w1, v1.y, a1.y);
    }
    if (e < end) {
        int s0 = g_srcs[e];
        float w0 = g_wsrt[e];
        float2 v0 = *(const float2*)(src + (size_t)s0 * 64 + lane * 2);
        a0.x = fmaf(w0, v0.x, a0.x); a0.y = fmaf(w0, v0.y, a0.y);
    }
    float2 r; r.x = a0.x + a1.x; r.y = a0.y + a1.y;
    *(float2*)(dst + (size_t)j * 64 + lane * 2) = r;
}

__global__ __launch_bounds__(256) void k_prop128(float* __restrict__ dst, const float* __restrict__ src) {
    int wrp = threadIdx.x >> 5, lane = threadIdx.x & 31;
    int j = blockIdx.x * 8 + wrp;
    if (j >= NN) return;
    int beg = g_off[j], end = g_off[j + 1];
    float4 a0 = {0.f,0.f,0.f,0.f}, a1 = {0.f,0.f,0.f,0.f};
    int e = beg;
    for (; e + 2 <= end; e += 2) {
        int s0 = g_srcs[e], s1 = g_srcs[e + 1];
        float w0 = g_wsrt[e], w1 = g_wsrt[e + 1];
        float4 v0 = *(const float4*)(src + (size_t)s0 * 128 + lane * 4);
        float4 v1 = *(const float4*)(src + (size_t)s1 * 128 + lane * 4);
        a0.x = fmaf(w0, v0.x, a0.x); a0.y = fmaf(w0, v0.y, a0.y);
        a0.z = fmaf(w0, v0.z, a0.z); a0.w = fmaf(w0, v0.w, a0.w);
        a1.x = fmaf(w1, v1.x, a1.x); a1.y = fmaf(w1, v1.y, a1.y);
        a1.z = fmaf(w1, v1.z, a1.z); a1.w = fmaf(w1, v1.w, a1.w);
    }
    if (e < end) {
        int s0 = g_srcs[e];
        float w0 = g_wsrt[e];
        float4 v0 = *(const float4*)(src + (size_t)s0 * 128 + lane * 4);
        a0.x = fmaf(w0, v0.x, a0.x); a0.y = fmaf(w0, v0.y, a0.y);
        a0.z = fmaf(w0, v0.z, a0.z); a0.w = fmaf(w0, v0.w, a0.w);
    }
    float4 r;
    r.x = a0.x + a1.x; r.y = a0.y + a1.y; r.z = a0.z + a1.z; r.w = a0.w + a1.w;
    *(float4*)(dst + (size_t)j * 128 + lane * 4) = r;
}

// tag3: dst = P src + add   (64 channels)
__global__ __launch_bounds__(256) void k_propadd64(float* __restrict__ dst, const float* __restrict__ src,
                                                   const float* __restrict__ add) {
    int wrp = threadIdx.x >> 5, lane = threadIdx.x & 31;
    int j = blockIdx.x * 8 + wrp;
    if (j >= NN) return;
    int beg = g_off[j], end = g_off[j + 1];
    float2 a0 = {0.f, 0.f}, a1 = {0.f, 0.f};
    int e = beg;
    for (; e + 2 <= end; e += 2) {
        int s0 = g_srcs[e], s1 = g_srcs[e + 1];
        float w0 = g_wsrt[e], w1 = g_wsrt[e + 1];
        float2 v0 = *(const float2*)(src + (size_t)s0 * 64 + lane * 2);
        float2 v1 = *(const float2*)(src + (size_t)s1 * 64 + lane * 2);
        a0.x = fmaf(w0, v0.x, a0.x); a0.y = fmaf(w0, v0.y, a0.y);
        a1.x = fmaf(w1, v1.x, a1.x); a1.y = fmaf(w1, v1.y, a1.y);
    }
    if (e < end) {
        int s0 = g_srcs[e];
        float w0 = g_wsrt[e];
        float2 v0 = *(const float2*)(src + (size_t)s0 * 64 + lane * 2);
        a0.x = fmaf(w0, v0.x, a0.x); a0.y = fmaf(w0, v0.y, a0.y);
    }
    float2 ad = *(const float2*)(add + (size_t)j * 64 + lane * 2);
    float2 r; r.x = a0.x + a1.x + ad.x; r.y = a0.y + a1.y + ad.y;
    *(float2*)(dst + (size_t)j * 64 + lane * 2) = r;
}

// tag3 final: z = log_softmax(P src + add + bias)
__global__ __launch_bounds__(256) void k_proplogsm(const float* __restrict__ src,
                                                   const float* __restrict__ add,
                                                   const float* __restrict__ bias) {
    int wrp = threadIdx.x >> 5, lane = threadIdx.x & 31;
    int j = blockIdx.x * 8 + wrp;
    if (j >= NN) return;
    int beg = g_off[j], end = g_off[j + 1];
    float2 a0 = {0.f, 0.f}, a1 = {0.f, 0.f};
    int e = beg;
    for (; e + 2 <= end; e += 2) {
        int s0 = g_srcs[e], s1 = g_srcs[e + 1];
        float w0 = g_wsrt[e], w1 = g_wsrt[e + 1];
        float2 v0 = *(const float2*)(src + (size_t)s0 * 64 + lane * 2);
        float2 v1 = *(const float2*)(src + (size_t)s1 * 64 + lane * 2);
        a0.x = fmaf(w0, v0.x, a0.x); a0.y = fmaf(w0, v0.y, a0.y);
        a1.x = fmaf(w1, v1.x, a1.x); a1.y = fmaf(w1, v1.y, a1.y);
    }
    if (e < end) {
        int s0 = g_srcs[e];
        float w0 = g_wsrt[e];
        float2 v0 = *(const float2*)(src + (size_t)s0 * 64 + lane * 2);
        a0.x = fmaf(w0, v0.x, a0.x); a0.y = fmaf(w0, v0.y, a0.y);
    }
    float2 ad = *(const float2*)(add + (size_t)j * 64 + lane * 2);
    float v0 = a0.x + a1.x + ad.x + bias[2 * lane];
    float v1 = a0.y + a1.y + ad.y + bias[2 * lane + 1];
    float m = fmaxf(v0, v1);
#pragma unroll
    for (int o = 16; o; o >>= 1) m = fmaxf(m, __shfl_xor_sync(0xffffffffu, m, o));
    float s = expf(v0 - m) + expf(v1 - m);
#pragma unroll
    for (int o = 16; o; o >>= 1) s += __shfl_xor_sync(0xffffffffu, s, o);
    float l = m + logf(s);
    g_z[j * 64 + 2 * lane]     = v0 - l;
    g_z[j * 64 + 2 * lane + 1] = v1 - l;
}

// ---------------- GEMM (FFMA2): dst[N,COUT] = f(A[N,Cin] @ W[Cin,COUT]) ----------------
// MODE 0: dst = prod ; MODE 1: dst += prod ; MODE 2: dst = addend + prod
// RELU: write max(val + bias, 0) to hdst instead of dst
template <int COUT, int MODE, bool RELU>
__global__ __launch_bounds__(256) void k_gemm(float* __restrict__ dst, const float* __restrict__ A,
                                              int astride, const float* __restrict__ W, int Cin,
                                              const float* __restrict__ addend,
                                              const float* __restrict__ bias,
                                              float* __restrict__ hdst) {
    constexpr int CPT = COUT / 32;            // couts per lane (4 or 2)
    __shared__ __align__(16) float As[16][64];
    __shared__ __align__(16) ull  Wd[16][COUT];   // each entry = {w, w}
    int tid = threadIdx.x, lane = tid & 31, wrp = tid >> 5;
    int row0 = blockIdx.x * 64;
    int rb = wrp * 8;

    ull acc[4][CPT];
#pragma unroll
    for (int r = 0; r < 4; r++)
#pragma unroll
        for (int c = 0; c < CPT; c++) acc[r][c] = 0ull;

    int lr = tid >> 2;          // 0..63 A row in tile
    int lk = (tid & 3) * 4;     // 0,4,8,12
    int grow = row0 + lr;
    const float* arow = A + (size_t)grow * astride;

    for (int k0 = 0; k0 < Cin; k0 += 16) {
#pragma unroll
        for (int i = 0; i < 4; i++) {
            int kk = lk + i;
            As[kk][lr] = (grow < NN) ? arow[k0 + kk] : 0.f;
        }
        constexpr int WE = 16 * COUT / 256;   // 8 or 4
#pragma unroll
        for (int i = 0; i < WE; i++) {
            int off = tid * WE + i;
            int kk = off / COUT, c = off - kk * COUT;
            float w = W[(size_t)(k0 + kk) * COUT + c];
            Wd[kk][c] = pack2(w, w);
        }
        __syncthreads();
#pragma unroll
        for (int kk = 0; kk < 16; kk++) {
            ulonglong2 pa0 = *(const ulonglong2*)&As[kk][rb];
            ulonglong2 pa1 = *(const ulonglong2*)&As[kk][rb + 4];
            ull ap[4] = {pa0.x, pa0.y, pa1.x, pa1.y};
            ull wp[CPT];
            if constexpr (CPT == 4) {
                ulonglong2 w01 = *(const ulonglong2*)&Wd[kk][lane * 4];
                ulonglong2 w23 = *(const ulonglong2*)&Wd[kk][lane * 4 + 2];
                wp[0] = w01.x; wp[1] = w01.y; wp[2] = w23.x; wp[3] = w23.y;
            } else {
                ulonglong2 w01 = *(const ulonglong2*)&Wd[kk][lane * 2];
                wp[0] = w01.x; wp[1] = w01.y;
            }
#pragma unroll
            for (int r = 0; r < 4; r++)
#pragma unroll
                for (int c = 0; c < CPT; c++)
                    acc[r][c] = ffma2(ap[r], wp[c], acc[r][c]);
        }
        __syncthreads();
    }

    // epilogue: acc[rp][c] holds rows (rb+2rp, rb+2rp+1), cout lane*CPT+c
#pragma unroll
    for (int rp = 0; rp < 4; rp++) {
        float vlo[CPT], vhi[CPT];
#pragma unroll
        for (int c = 0; c < CPT; c++) unpack2(acc[rp][c], vlo[c], vhi[c]);
#pragma unroll
        for (int half = 0; half < 2; half++) {
            int row = row0 + rb + rp * 2 + half;
            if (row >= NN) continue;
            float* vals = half ? vhi : vlo;
            size_t base = (size_t)row * COUT + lane * CPT;
            if constexpr (MODE == 1) {
#pragma unroll
                for (int c = 0; c < CPT; c++) vals[c] += dst[base + c];
            } else if constexpr (MODE == 2) {
#pragma unroll
                for (int c = 0; c < CPT; c++) vals[c] += addend[base + c];
            }
            if constexpr (RELU) {
#pragma unroll
                for (int c = 0; c < CPT; c++)
                    hdst[base + c] = fmaxf(vals[c] + bias[lane * CPT + c], 0.f);
            } else {
                if constexpr (CPT == 4) {
                    float4 v; v.x = vals[0]; v.y = vals[1]; v.z = vals[2]; v.w = vals[3];
                    *(float4*)(dst + base) = v;
                } else {
                    float2 v; v.x = vals[0]; v.y = vals[1];
                    *(float2*)(dst + base) = v;
                }
            }
        }
    }
}

// ---------------- down MLP + output write ----------------
__global__ __launch_bounds__(256) void k_down(float* __restrict__ out,
                                              const float* __restrict__ w1, const float* __restrict__ b1,
                                              const float* __restrict__ w2, const float* __restrict__ b2) {
    int wrp = threadIdx.x >> 5, lane = threadIdx.x & 31;
    int j = blockIdx.x * 8 + wrp;
    if (j >= NN) return;
    float z0 = g_z[j * 64 + lane];
    float z1 = g_z[j * 64 + 32 + lane];
    out[NN + j * 64 + lane] = z0;
    out[NN + j * 64 + 32 + lane] = z1;
    float d = z0 * w1[lane] + z1 * w1[32 + lane];
#pragma unroll
    for (int o = 16; o; o >>= 1) d += __shfl_xor_sync(0xffffffffu, d, o);
    if (lane == 0) out[j] = gelu_exact(d + b1[0]) * w2[0] + b2[0];
}

// ---------------- host orchestration ----------------
extern "C" void kernel_launch(void* const* d_in, const int* in_sizes, int n_in,
                              void* d_out, int out_size) {
    const float* x      = (const float*)d_in[0];
    const float* pos    = (const float*)d_in[1];
    const float* ea     = (const float*)d_in[2];
    const float* up_w1  = (const float*)d_in[3];
    const float* up_b1  = (const float*)d_in[4];
    const float* up_w2  = (const float*)d_in[5];
    const float* up_b2  = (const float*)d_in[6];
    const float* c1_w   = (const float*)d_in[7];
    const float* c1_b   = (const float*)d_in[8];
    const float* c2_w   = (const float*)d_in[9];
    const float* c2_b   = (const float*)d_in[10];
    const float* c3_w   = (const float*)d_in[11];
    const float* c3_b   = (const float*)d_in[12];
    const float* dw1    = (const float*)d_in[13];
    const float* db1    = (const float*)d_in[14];
    const float* dw2    = (const float*)d_in[15];
    const float* db2    = (const float*)d_in[16];
    const int*   ei     = (const int*)d_in[17];
    const int* row = ei;
    const int* col = ei + EE;

    float *z, *h, *b0, *b1, *acc, *y3, *pp1, *pp2, *pp3, *posacc;
    cudaGetSymbolAddress((void**)&z,      g_z);
    cudaGetSymbolAddress((void**)&h,      g_h);
    cudaGetSymbolAddress((void**)&b0,     g_b0);
    cudaGetSymbolAddress((void**)&b1,     g_b1);
    cudaGetSymbolAddress((void**)&acc,    g_acc);
    cudaGetSymbolAddress((void**)&y3,     g_y3);
    cudaGetSymbolAddress((void**)&pp1,    g_pp1);
    cudaGetSymbolAddress((void**)&pp2,    g_pp2);
    cudaGetSymbolAddress((void**)&pp3,    g_pp3);
    cudaGetSymbolAddress((void**)&posacc, g_posacc);

    const int GN = (NN + 255) / 256;
    const int GE = (EE + 255) / 256;
    const int GW = (NN + 7) / 8;       // warp-per-node grids
    const int GG = (NN + 63) / 64;     // gemm grids
    const int GP = (NN * HID + 255) / 256;

    // --- graph setup (CSR by destination, gcn norm) ---
    k_zero<<<GN, 256>>>();
    k_hist<<<GE, 256>>>(col, ea);
    k_dinv<<<GN, 256>>>();
    k_scan<<<1, 1024>>>();
    k_cursor<<<GN, 256>>>();
    k_scatter<<<GE, 256>>>(row, col, ea);

    // --- iteration-invariant pos hops + pos contribution to tag1 ---
    k_prop3<<<GN, 256>>>(pp1, pos);
    k_prop3<<<GN, 256>>>(pp2, pp1);
    k_prop3<<<GN, 256>>>(pp3, pp2);
    k_posacc<<<GP, 256>>>(pos, c1_w);

    // --- up MLP -> z0 ---
    k_up<<<(NN + 3) / 4, 256>>>(x, up_w1, up_b1, up_w2, up_b2);

    const size_t W1S = 67 * 128;   // c1_w per-k stride (z-part = first 64 rows)
    // --- 21 gnn applications (20 fixed-point + 1 phantom) ---
    for (int it = 0; it < 21; it++) {
        // tag1: Cin=64 (z) + precomputed pos part, COUT=128
        k_gemm<128, 2, false><<<GG, 256>>>(acc, z, 64, c1_w, 64, posacc, nullptr, nullptr);
        k_prop64<<<GW, 256>>>(b0, z);
        k_gemm<128, 1, false><<<GG, 256>>>(acc, b0, 64, c1_w + 1 * W1S, 64, nullptr, nullptr, nullptr);
        k_prop64<<<GW, 256>>>(b1, b0);
        k_gemm<128, 1, false><<<GG, 256>>>(acc, b1, 64, c1_w + 2 * W1S, 64, nullptr, nullptr, nullptr);
        k_prop64<<<GW, 256>>>(b0, b1);
        k_gemm<128, 1, true><<<GG, 256>>>(acc, b0, 64, c1_w + 3 * W1S, 64, nullptr, c1_b, h);

        // tag2: 128 -> 128, prop-first
        k_gemm<128, 0, false><<<GG, 256>>>(acc, h, 128, c2_w, 128, nullptr, nullptr, nullptr);
        k_prop128<<<GW, 256>>>(b0, h);
        k_gemm<128, 1, false><<<GG, 256>>>(acc, b0, 128, c2_w + 1 * 128 * 128, 128, nullptr, nullptr, nullptr);
        k_prop128<<<GW, 256>>>(b1, b0);
        k_gemm<128, 1, false><<<GG, 256>>>(acc, b1, 128, c2_w + 2 * 128 * 128, 128, nullptr, nullptr, nullptr);
        k_prop128<<<GW, 256>>>(b0, b1);
        k_gemm<128, 1, true><<<GG, 256>>>(acc, b0, 128, c2_w + 3 * 128 * 128, 128, nullptr, c2_b, h);

        // tag3: 128 -> 64, prop-AFTER-gemm (propagation commutes with channel map)
        k_gemm<64, 0, false><<<GG, 256>>>(acc, h, 128, c3_w, 128, nullptr, nullptr, nullptr);              // y0
        k_gemm<64, 0, false><<<GG, 256>>>(b0,  h, 128, c3_w + 1 * 128 * 64, 128, nullptr, nullptr, nullptr); // y1
        k_gemm<64, 0, false><<<GG, 256>>>(b1,  h, 128, c3_w + 2 * 128 * 64, 128, nullptr, nullptr, nullptr); // y2
        k_gemm<64, 0, false><<<GG, 256>>>(y3,  h, 128, c3_w + 3 * 128 * 64, 128, nullptr, nullptr, nullptr); // y3
        k_propadd64<<<GW, 256>>>(h,  y3, b1);   // t1 = P y3 + y2
        k_propadd64<<<GW, 256>>>(y3, h,  b0);   // t2 = P t1 + y1
        k_proplogsm<<<GW, 256>>>(y3, acc, c3_b); // z = logsm(P t2 + y0 + bias)
    }

    // --- down MLP + write (out, z_star) ---
    k_down<<<GW, 256>>>((float*)d_out, dw1, db1, dw2, db2);

    (void)in_sizes; (void)n_in; (void)out_size;
}

// round 4
// speedup vs baseline: 1.4548x; 1.4548x over previous
#include <cuda_runtime.h>
#include <cuda_bf16.h>
#include <math.h>

#define NN 50000
#define EE 800000
#define EMB 64
#define HID 128

// ---------------- scratch (device globals; no allocation allowed) ----------------
__device__ float g_deg[NN];
__device__ float g_dinv[NN];
__device__ int   g_cnt[NN];
__device__ int   g_off[NN + 1];
__device__ int   g_cur[NN];
__device__ int   g_srcs[EE];
__device__ float g_wsrt[EE];

__device__ float g_z[NN * EMB];       // state z
__device__ float g_h[NN * HID];       // tag output (relu'd)
__device__ float g_p1[NN * HID];      // hop buffers (used at 64 or 128 width)
__device__ float g_p2[NN * HID];
__device__ float g_p3[NN * HID];
__device__ float g_y0[NN * EMB];      // tag3 per-k GEMM outputs
__device__ float g_y1[NN * EMB];
__device__ float g_y2[NN * EMB];
__device__ float g_y3[NN * EMB];
__device__ float g_pp1[NN * 3];       // P pos
__device__ float g_pp2[NN * 3];       // P^2 pos
__device__ float g_pp3[NN * 3];       // P^3 pos
__device__ float g_posacc[NN * HID];  // sum_k (P^k pos) @ W1_k[64:67,:]

__device__ __forceinline__ float gelu_exact(float x) {
    return 0.5f * x * (1.0f + erff(x * 0.70710678118654752f));
}

// ---------------- setup kernels ----------------
__global__ void k_zero() {
    int i = blockIdx.x * blockDim.x + threadIdx.x;
    if (i < NN) { g_deg[i] = 0.f; g_cnt[i] = 0; }
}

__global__ void k_hist(const int* __restrict__ col, const float* __restrict__ ea) {
    int e = blockIdx.x * blockDim.x + threadIdx.x;
    if (e < EE) {
        int c = col[e];
        atomicAdd(&g_deg[c], ea[e]);
        atomicAdd(&g_cnt[c], 1);
    }
}

__global__ void k_dinv() {
    int i = blockIdx.x * blockDim.x + threadIdx.x;
    if (i < NN) {
        float d = g_deg[i];
        g_dinv[i] = (d > 0.f) ? rsqrtf(d) : 0.f;
    }
}

__global__ void k_scan() {
    __shared__ int sh[1024];
    int tid = threadIdx.x;
    int carry = 0;
    for (int base = 0; base < NN; base += 1024) {
        int i = base + tid;
        int v = (i < NN) ? g_cnt[i] : 0;
        sh[tid] = v;
        __syncthreads();
        for (int ofs = 1; ofs < 1024; ofs <<= 1) {
            int t = (tid >= ofs) ? sh[tid - ofs] : 0;
            __syncthreads();
            sh[tid] += t;
            __syncthreads();
        }
        if (i < NN) g_off[i] = carry + sh[tid] - v;
        carry += sh[1023];
        __syncthreads();
    }
    if (tid == 0) g_off[NN] = carry;
}

__global__ void k_cursor() {
    int i = blockIdx.x * blockDim.x + threadIdx.x;
    if (i < NN) g_cur[i] = g_off[i];
}

__global__ void k_scatter(const int* __restrict__ row, const int* __restrict__ col,
                          const float* __restrict__ ea) {
    int e = blockIdx.x * blockDim.x + threadIdx.x;
    if (e < EE) {
        int r = row[e], c = col[e];
        int p = atomicAdd(&g_cur[c], 1);
        g_srcs[p] = r;
        g_wsrt[p] = g_dinv[r] * ea[e] * g_dinv[c];
    }
}

// ---------------- pos hops (3 channels, thread per node) ----------------
__global__ void k_prop3(float* __restrict__ dst, const float* __restrict__ src) {
    int j = blockIdx.x * blockDim.x + threadIdx.x;
    if (j >= NN) return;
    int beg = g_off[j], end = g_off[j + 1];
    float a0 = 0.f, a1 = 0.f, a2 = 0.f;
    for (int e = beg; e < end; e++) {
        int s = g_srcs[e];
        float w = g_wsrt[e];
        a0 += w * src[s * 3 + 0];
        a1 += w * src[s * 3 + 1];
        a2 += w * src[s * 3 + 2];
    }
    dst[j * 3 + 0] = a0; dst[j * 3 + 1] = a1; dst[j * 3 + 2] = a2;
}

// posacc[n,c] = sum_{k=0..3} sum_{j=0..2} ppk[n,j] * c1_w[k][64+j][c]
__global__ void k_posacc(const float* __restrict__ pos, const float* __restrict__ c1w) {
    int idx = blockIdx.x * blockDim.x + threadIdx.x;
    if (idx >= NN * HID) return;
    int n = idx >> 7, c = idx & 127;
    const float* pps[4] = {pos, g_pp1, g_pp2, g_pp3};
    float acc = 0.f;
#pragma unroll
    for (int k = 0; k < 4; k++) {
        const float* pp = pps[k] + n * 3;
        const float* wr = c1w + k * 67 * 128 + 64 * 128 + c;
        acc += pp[0] * wr[0] + pp[1] * wr[128] + pp[2] * wr[256];
    }
    g_posacc[idx] = acc;
}

// ---------------- up MLP: z0 = gelu(x@W1+b1)@W2+b2 ----------------
__global__ __launch_bounds__(256) void k_up(const float* __restrict__ x,
                                            const float* __restrict__ w1, const float* __restrict__ b1,
                                            const float* __restrict__ w2, const float* __restrict__ b2) {
    __shared__ float sw2[64 * 64];
    __shared__ float hid[4][64];
    int tid = threadIdx.x;
#pragma unroll
    for (int i = 0; i < 16; i++) sw2[tid * 16 + i] = w2[tid * 16 + i];
    int local = tid >> 6;
    int c = tid & 63;
    int node = blockIdx.x * 4 + local;
    float h = 0.f;
    if (node < NN) {
        h = b1[c];
#pragma unroll
        for (int i = 0; i < 4; i++) h += x[node * 4 + i] * w1[i * 64 + c];
        h = gelu_exact(h);
    }
    hid[local][c] = h;
    __syncthreads();
    if (node < NN) {
        float o = b2[c];
#pragma unroll
        for (int j = 0; j < 64; j++) o += hid[local][j] * sw2[j * 64 + c];
        g_z[node * 64 + c] = o;
    }
}

// ---------------- propagation kernels (CSR, warp per node) ----------------
__global__ __launch_bounds__(256) void k_prop64(float* __restrict__ dst, const float* __restrict__ src) {
    int wrp = threadIdx.x >> 5, lane = threadIdx.x & 31;
    int j = blockIdx.x * 8 + wrp;
    if (j >= NN) return;
    int beg = g_off[j], end = g_off[j + 1];
    float2 a0 = {0.f, 0.f}, a1 = {0.f, 0.f};
    int e = beg;
    for (; e + 2 <= end; e += 2) {
        int s0 = g_srcs[e], s1 = g_srcs[e + 1];
        float w0 = g_wsrt[e], w1 = g_wsrt[e + 1];
        float2 v0 = *(const float2*)(src + (size_t)s0 * 64 + lane * 2);
        float2 v1 = *(const float2*)(src + (size_t)s1 * 64 + lane * 2);
        a0.x = fmaf(w0, v0.x, a0.x); a0.y = fmaf(w0, v0.y, a0.y);
        a1.x = fmaf(w1, v1.x, a1.x); a1.y = fmaf(w1, v1.y, a1.y);
    }
    if (e < end) {
        int s0 = g_srcs[e];
        float w0 = g_wsrt[e];
        float2 v0 = *(const float2*)(src + (size_t)s0 * 64 + lane * 2);
        a0.x = fmaf(w0, v0.x, a0.x); a0.y = fmaf(w0, v0.y, a0.y);
    }
    float2 r; r.x = a0.x + a1.x; r.y = a0.y + a1.y;
    *(float2*)(dst + (size_t)j * 64 + lane * 2) = r;
}

__global__ __launch_bounds__(256) void k_prop128(float* __restrict__ dst, const float* __restrict__ src) {
    int wrp = threadIdx.x >> 5, lane = threadIdx.x & 31;
    int j = blockIdx.x * 8 + wrp;
    if (j >= NN) return;
    int beg = g_off[j], end = g_off[j + 1];
    float4 a0 = {0.f,0.f,0.f,0.f}, a1 = {0.f,0.f,0.f,0.f};
    int e = beg;
    for (; e + 2 <= end; e += 2) {
        int s0 = g_srcs[e], s1 = g_srcs[e + 1];
        float w0 = g_wsrt[e], w1 = g_wsrt[e + 1];
        float4 v0 = *(const float4*)(src + (size_t)s0 * 128 + lane * 4);
        float4 v1 = *(const float4*)(src + (size_t)s1 * 128 + lane * 4);
        a0.x = fmaf(w0, v0.x, a0.x); a0.y = fmaf(w0, v0.y, a0.y);
        a0.z = fmaf(w0, v0.z, a0.z); a0.w = fmaf(w0, v0.w, a0.w);
        a1.x = fmaf(w1, v1.x, a1.x); a1.y = fmaf(w1, v1.y, a1.y);
        a1.z = fmaf(w1, v1.z, a1.z); a1.w = fmaf(w1, v1.w, a1.w);
    }
    if (e < end) {
        int s0 = g_srcs[e];
        float w0 = g_wsrt[e];
        float4 v0 = *(const float4*)(src + (size_t)s0 * 128 + lane * 4);
        a0.x = fmaf(w0, v0.x, a0.x); a0.y = fmaf(w0, v0.y, a0.y);
        a0.z = fmaf(w0, v0.z, a0.z); a0.w = fmaf(w0, v0.w, a0.w);
    }
    float4 r;
    r.x = a0.x + a1.x; r.y = a0.y + a1.y; r.z = a0.z + a1.z; r.w = a0.w + a1.w;
    *(float4*)(dst + (size_t)j * 128 + lane * 4) = r;
}

// tag3: dst = P src + add   (64 channels)
__global__ __launch_bounds__(256) void k_propadd64(float* __restrict__ dst, const float* __restrict__ src,
                                                   const float* __restrict__ add) {
    int wrp = threadIdx.x >> 5, lane = threadIdx.x & 31;
    int j = blockIdx.x * 8 + wrp;
    if (j >= NN) return;
    int beg = g_off[j], end = g_off[j + 1];
    float2 a0 = {0.f, 0.f}, a1 = {0.f, 0.f};
    int e = beg;
    for (; e + 2 <= end; e += 2) {
        int s0 = g_srcs[e], s1 = g_srcs[e + 1];
        float w0 = g_wsrt[e], w1 = g_wsrt[e + 1];
        float2 v0 = *(const float2*)(src + (size_t)s0 * 64 + lane * 2);
        float2 v1 = *(const float2*)(src + (size_t)s1 * 64 + lane * 2);
        a0.x = fmaf(w0, v0.x, a0.x); a0.y = fmaf(w0, v0.y, a0.y);
        a1.x = fmaf(w1, v1.x, a1.x); a1.y = fmaf(w1, v1.y, a1.y);
    }
    if (e < end) {
        int s0 = g_srcs[e];
        float w0 = g_wsrt[e];
        float2 v0 = *(const float2*)(src + (size_t)s0 * 64 + lane * 2);
        a0.x = fmaf(w0, v0.x, a0.x); a0.y = fmaf(w0, v0.y, a0.y);
    }
    float2 ad = *(const float2*)(add + (size_t)j * 64 + lane * 2);
    float2 r; r.x = a0.x + a1.x + ad.x; r.y = a0.y + a1.y + ad.y;
    *(float2*)(dst + (size_t)j * 64 + lane * 2) = r;
}

// tag3 final: z = log_softmax(P src + add + bias)
__global__ __launch_bounds__(256) void k_proplogsm(const float* __restrict__ src,
                                                   const float* __restrict__ add,
                                                   const float* __restrict__ bias) {
    int wrp = threadIdx.x >> 5, lane = threadIdx.x & 31;
    int j = blockIdx.x * 8 + wrp;
    if (j >= NN) return;
    int beg = g_off[j], end = g_off[j + 1];
    float2 a0 = {0.f, 0.f}, a1 = {0.f, 0.f};
    int e = beg;
    for (; e + 2 <= end; e += 2) {
        int s0 = g_srcs[e], s1 = g_srcs[e + 1];
        float w0 = g_wsrt[e], w1 = g_wsrt[e + 1];
        float2 v0 = *(const float2*)(src + (size_t)s0 * 64 + lane * 2);
        float2 v1 = *(const float2*)(src + (size_t)s1 * 64 + lane * 2);
        a0.x = fmaf(w0, v0.x, a0.x); a0.y = fmaf(w0, v0.y, a0.y);
        a1.x = fmaf(w1, v1.x, a1.x); a1.y = fmaf(w1, v1.y, a1.y);
    }
    if (e < end) {
        int s0 = g_srcs[e];
        float w0 = g_wsrt[e];
        float2 v0 = *(const float2*)(src + (size_t)s0 * 64 + lane * 2);
        a0.x = fmaf(w0, v0.x, a0.x); a0.y = fmaf(w0, v0.y, a0.y);
    }
    float2 ad = *(const float2*)(add + (size_t)j * 64 + lane * 2);
    float v0 = a0.x + a1.x + ad.x + bias[2 * lane];
    float v1 = a0.y + a1.y + ad.y + bias[2 * lane + 1];
    float m = fmaxf(v0, v1);
#pragma unroll
    for (int o = 16; o; o >>= 1) m = fmaxf(m, __shfl_xor_sync(0xffffffffu, m, o));
    float s = expf(v0 - m) + expf(v1 - m);
#pragma unroll
    for (int o = 16; o; o >>= 1) s += __shfl_xor_sync(0xffffffffu, s, o);
    float l = m + logf(s);
    g_z[j * 64 + 2 * lane]     = v0 - l;
    g_z[j * 64 + 2 * lane + 1] = v1 - l;
}

// ---------------- fused 4-hop GEMM (scalar FFMA inner loop, COUT=128) -------------
// h = relu( sum_{k=0..3} A_k @ W_k  [+ addend] + bias )
// W_k = W + k*wstride, rows [CinH,128] row-major
template <int CinH, bool ADDEND>
__global__ __launch_bounds__(256) void k_gemm4(const float* __restrict__ A0, const float* __restrict__ A1,
                                               const float* __restrict__ A2, const float* __restrict__ A3,
                                               const float* __restrict__ W, size_t wstride,
                                               const float* __restrict__ addend,
                                               const float* __restrict__ bias,
                                               float* __restrict__ hdst) {
    __shared__ __align__(16) float As[16][64];
    __shared__ __align__(16) float Ws[16][128];
    int tid = threadIdx.x, lane = tid & 31, wrp = tid >> 5;
    int row0 = blockIdx.x * 64;
    int rb = wrp * 8;
    float acc[8][4];
#pragma unroll
    for (int r = 0; r < 8; r++)
#pragma unroll
        for (int c = 0; c < 4; c++) acc[r][c] = 0.f;

    int lr = tid >> 2;          // 0..63 A row in tile
    int lk = (tid & 3) * 4;     // 0,4,8,12
    int grow = row0 + lr;
    bool rowok = (grow < NN);
    const float* srcs[4] = {A0, A1, A2, A3};

#pragma unroll 1
    for (int hop = 0; hop < 4; hop++) {
        const float* arow = srcs[hop] + (size_t)grow * CinH;
        const float* Wk = W + hop * wstride;
#pragma unroll 1
        for (int k0 = 0; k0 < CinH; k0 += 16) {
#pragma unroll
            for (int i = 0; i < 4; i++) {
                int kk = lk + i;
                As[kk][lr] = rowok ? arow[k0 + kk] : 0.f;
            }
#pragma unroll
            for (int i = 0; i < 8; i++) {
                int off = tid * 8 + i;
                int kk = off >> 7, c = off & 127;
                Ws[kk][c] = Wk[(size_t)(k0 + kk) * 128 + c];
            }
            __syncthreads();
#pragma unroll
            for (int kk = 0; kk < 16; kk++) {
                float a[8];
                float4 a0 = *(const float4*)&As[kk][rb];
                float4 a1 = *(const float4*)&As[kk][rb + 4];
                a[0] = a0.x; a[1] = a0.y; a[2] = a0.z; a[3] = a0.w;
                a[4] = a1.x; a[5] = a1.y; a[6] = a1.z; a[7] = a1.w;
                float4 wv = *(const float4*)&Ws[kk][lane * 4];
                float w[4] = {wv.x, wv.y, wv.z, wv.w};
#pragma unroll
                for (int r = 0; r < 8; r++)
#pragma unroll
                    for (int c = 0; c < 4; c++)
                        acc[r][c] = fmaf(a[r], w[c], acc[r][c]);
            }
            __syncthreads();
        }
    }

    float4 bv = *(const float4*)&bias[lane * 4];
    float bb[4] = {bv.x, bv.y, bv.z, bv.w};
#pragma unroll
    for (int r = 0; r < 8; r++) {
        int row = row0 + rb + r;
        if (row < NN) {
            size_t base = (size_t)row * 128 + lane * 4;
            float v[4];
            if constexpr (ADDEND) {
                float4 ad = *(const float4*)&addend[base];
                v[0] = acc[r][0] + ad.x; v[1] = acc[r][1] + ad.y;
                v[2] = acc[r][2] + ad.z; v[3] = acc[r][3] + ad.w;
            } else {
                v[0] = acc[r][0]; v[1] = acc[r][1]; v[2] = acc[r][2]; v[3] = acc[r][3];
            }
            float4 o;
            o.x = fmaxf(v[0] + bb[0], 0.f);
            o.y = fmaxf(v[1] + bb[1], 0.f);
            o.z = fmaxf(v[2] + bb[2], 0.f);
            o.w = fmaxf(v[3] + bb[3], 0.f);
            *(float4*)(hdst + base) = o;
        }
    }
}

// ---------------- paired GEMM: out0 = A@W0, out1 = A@W1 (A [N,128], W [128,64]) ----
__global__ __launch_bounds__(256) void k_gemm_pair(const float* __restrict__ A,
                                                   const float* __restrict__ W0, const float* __restrict__ W1,
                                                   float* __restrict__ out0, float* __restrict__ out1) {
    __shared__ __align__(16) float As[16][64];
    __shared__ __align__(16) float Ws[16][128];
    int tid = threadIdx.x, lane = tid & 31, wrp = tid >> 5;
    int row0 = blockIdx.x * 64;
    int rb = wrp * 8;
    float acc[8][4];
#pragma unroll
    for (int r = 0; r < 8; r++)
#pragma unroll
        for (int c = 0; c < 4; c++) acc[r][c] = 0.f;

    int lr = tid >> 2;
    int lk = (tid & 3) * 4;
    int grow = row0 + lr;
    bool rowok = (grow < NN);
    const float* arow = A + (size_t)grow * 128;

#pragma unroll 1
    for (int k0 = 0; k0 < 128; k0 += 16) {
#pragma unroll
        for (int i = 0; i < 4; i++) {
            int kk = lk + i;
            As[kk][lr] = rowok ? arow[k0 + kk] : 0.f;
        }
#pragma unroll
        for (int i = 0; i < 8; i++) {
            int off = tid * 8 + i;
            int kk = off >> 7, c = off & 127;
            const float* Wp = (c < 64) ? W0 : W1;
            Ws[kk][c] = Wp[(size_t)(k0 + kk) * 64 + (c & 63)];
        }
        __syncthreads();
#pragma unroll
        for (int kk = 0; kk < 16; kk++) {
            float a[8];
            float4 a0 = *(const float4*)&As[kk][rb];
            float4 a1 = *(const float4*)&As[kk][rb + 4];
            a[0] = a0.x; a[1] = a0.y; a[2] = a0.z; a[3] = a0.w;
            a[4] = a1.x; a[5] = a1.y; a[6] = a1.z; a[7] = a1.w;
            float4 wv = *(const float4*)&Ws[kk][lane * 4];
            float w[4] = {wv.x, wv.y, wv.z, wv.w};
#pragma unroll
            for (int r = 0; r < 8; r++)
#pragma unroll
                for (int c = 0; c < 4; c++)
                    acc[r][c] = fmaf(a[r], w[c], acc[r][c]);
        }
        __syncthreads();
    }

    // lanes 0..15 -> out0 couts (lane*4), lanes 16..31 -> out1 couts ((lane-16)*4)
    float* outp = (lane < 16) ? out0 : out1;
    int cl = (lane & 15) * 4;
#pragma unroll
    for (int r = 0; r < 8; r++) {
        int row = row0 + rb + r;
        if (row < NN) {
            float4 v; v.x = acc[r][0]; v.y = acc[r][1]; v.z = acc[r][2]; v.w = acc[r][3];
            *(float4*)(outp + (size_t)row * 64 + cl) = v;
        }
    }
}

// ---------------- down MLP + output write ----------------
__global__ __launch_bounds__(256) void k_down(float* __restrict__ out,
                                              const float* __restrict__ w1, const float* __restrict__ b1,
                                              const float* __restrict__ w2, const float* __restrict__ b2) {
    int wrp = threadIdx.x >> 5, lane = threadIdx.x & 31;
    int j = blockIdx.x * 8 + wrp;
    if (j >= NN) return;
    float z0 = g_z[j * 64 + lane];
    float z1 = g_z[j * 64 + 32 + lane];
    out[NN + j * 64 + lane] = z0;
    out[NN + j * 64 + 32 + lane] = z1;
    float d = z0 * w1[lane] + z1 * w1[32 + lane];
#pragma unroll
    for (int o = 16; o; o >>= 1) d += __shfl_xor_sync(0xffffffffu, d, o);
    if (lane == 0) out[j] = gelu_exact(d + b1[0]) * w2[0] + b2[0];
}

// ---------------- host orchestration ----------------
extern "C" void kernel_launch(void* const* d_in, const int* in_sizes, int n_in,
                              void* d_out, int out_size) {
    const float* x      = (const float*)d_in[0];
    const float* pos    = (const float*)d_in[1];
    const float* ea     = (const float*)d_in[2];
    const float* up_w1  = (const float*)d_in[3];
    const float* up_b1  = (const float*)d_in[4];
    const float* up_w2  = (const float*)d_in[5];
    const float* up_b2  = (const float*)d_in[6];
    const float* c1_w   = (const float*)d_in[7];
    const float* c1_b   = (const float*)d_in[8];
    const float* c2_w   = (const float*)d_in[9];
    const float* c2_b   = (const float*)d_in[10];
    const float* c3_w   = (const float*)d_in[11];
    const float* c3_b   = (const float*)d_in[12];
    const float* dw1    = (const float*)d_in[13];
    const float* db1    = (const float*)d_in[14];
    const float* dw2    = (const float*)d_in[15];
    const float* db2    = (const float*)d_in[16];
    const int*   ei     = (const int*)d_in[17];
    const int* row = ei;
    const int* col = ei + EE;

    float *z, *h, *p1, *p2, *p3, *y0, *y1, *y2, *y3, *pp1, *pp2, *pp3, *posacc;
    cudaGetSymbolAddress((void**)&z,      g_z);
    cudaGetSymbolAddress((void**)&h,      g_h);
    cudaGetSymbolAddress((void**)&p1,     g_p1);
    cudaGetSymbolAddress((void**)&p2,     g_p2);
    cudaGetSymbolAddress((void**)&p3,     g_p3);
    cudaGetSymbolAddress((void**)&y0,     g_y0);
    cudaGetSymbolAddress((void**)&y1,     g_y1);
    cudaGetSymbolAddress((void**)&y2,     g_y2);
    cudaGetSymbolAddress((void**)&y3,     g_y3);
    cudaGetSymbolAddress((void**)&pp1,    g_pp1);
    cudaGetSymbolAddress((void**)&pp2,    g_pp2);
    cudaGetSymbolAddress((void**)&pp3,    g_pp3);
    cudaGetSymbolAddress((void**)&posacc, g_posacc);

    const int GN = (NN + 255) / 256;
    const int GE = (EE + 255) / 256;
    const int GW = (NN + 7) / 8;       // warp-per-node grids
    const int GG = (NN + 63) / 64;     // gemm grids
    const int GP = (NN * HID + 255) / 256;

    // --- graph setup (CSR by destination, gcn norm) ---
    k_zero<<<GN, 256>>>();
    k_hist<<<GE, 256>>>(col, ea);
    k_dinv<<<GN, 256>>>();
    k_scan<<<1, 1024>>>();
    k_cursor<<<GN, 256>>>();
    k_scatter<<<GE, 256>>>(row, col, ea);

    // --- iteration-invariant pos hops + pos contribution to tag1 ---
    k_prop3<<<GN, 256>>>(pp1, pos);
    k_prop3<<<GN, 256>>>(pp2, pp1);
    k_prop3<<<GN, 256>>>(pp3, pp2);
    k_posacc<<<GP, 256>>>(pos, c1_w);

    // --- up MLP -> z0 ---
    k_up<<<(NN + 3) / 4, 256>>>(x, up_w1, up_b1, up_w2, up_b2);

    const size_t W1S = 67 * 128;     // c1_w per-k stride (z-part = first 64 rows)
    const size_t W2S = 128 * 128;
    const size_t W3S = 128 * 64;

    // --- 21 gnn applications (20 fixed-point + 1 phantom) ---
    for (int it = 0; it < 21; it++) {
        // tag1: hops on z (64ch), fused GEMM -> h (relu, +posacc)
        k_prop64<<<GW, 256>>>(p1, z);
        k_prop64<<<GW, 256>>>(p2, p1);
        k_prop64<<<GW, 256>>>(p3, p2);
        k_gemm4<64, true><<<GG, 256>>>(z, p1, p2, p3, c1_w, W1S, posacc, c1_b, h);

        // tag2: hops on h (128ch), fused GEMM -> h (relu)
        k_prop128<<<GW, 256>>>(p1, h);
        k_prop128<<<GW, 256>>>(p2, p1);
        k_prop128<<<GW, 256>>>(p3, p2);
        k_gemm4<128, false><<<GG, 256>>>(h, p1, p2, p3, c2_w, W2S, nullptr, c2_b, h);

        // tag3: GEMMs first (prop commutes with channel map), then 64ch prop chain
        k_gemm_pair<<<GG, 256>>>(h, c3_w,           c3_w + 1 * W3S, y0, y1);
        k_gemm_pair<<<GG, 256>>>(h, c3_w + 2 * W3S, c3_w + 3 * W3S, y2, y3);
        k_propadd64<<<GW, 256>>>(p1, y3, y2);     // t1 = P y3 + y2
        k_propadd64<<<GW, 256>>>(p2, p1, y1);     // t2 = P t1 + y1
        k_proplogsm<<<GW, 256>>>(p2, y0, c3_b);   // z = logsm(P t2 + y0 + b)
    }

    // --- down MLP + write (out, z_star) ---
    k_down<<<GW, 256>>>((float*)d_out, dw1, db1, dw2, db2);

    (void)in_sizes; (void)n_in; (void)out_size;
}

// round 5
// speedup vs baseline: 1.4585x; 1.0026x over previous
#include <cuda_runtime.h>
#include <cuda_bf16.h>
#include <math.h>

#define NN 50000
#define EE 800000
#define EMB 64
#define HID 128

// ---------------- scratch (device globals; no allocation allowed) ----------------
__device__ float g_deg[NN];
__device__ float g_dinv[NN];
__device__ int   g_cnt[NN];
__device__ int   g_off[NN + 1];
__device__ int   g_cur[NN];
__device__ int   g_srcs[EE];
__device__ float g_wsrt[EE];

__device__ float g_z[NN * EMB];       // state z
__device__ float g_h[NN * HID];       // tag output (relu'd)
__device__ float g_p1[NN * HID];      // hop buffers (used at 64 or 128 width)
__device__ float g_p2[NN * HID];
__device__ float g_p3[NN * HID];
__device__ float g_y0[NN * EMB];      // tag3 per-k GEMM outputs
__device__ float g_y1[NN * EMB];
__device__ float g_y2[NN * EMB];
__device__ float g_y3[NN * EMB];
__device__ float g_pp1[NN * 3];       // P pos
__device__ float g_pp2[NN * 3];       // P^2 pos
__device__ float g_pp3[NN * 3];       // P^3 pos
__device__ float g_posacc[NN * HID];  // sum_k (P^k pos) @ W1_k[64:67,:]

__device__ __forceinline__ float gelu_exact(float x) {
    return 0.5f * x * (1.0f + erff(x * 0.70710678118654752f));
}

// ---------------- setup kernels ----------------
__global__ void k_zero() {
    int i = blockIdx.x * blockDim.x + threadIdx.x;
    if (i < NN) { g_deg[i] = 0.f; g_cnt[i] = 0; }
}

__global__ void k_hist(const int* __restrict__ col, const float* __restrict__ ea) {
    int e = blockIdx.x * blockDim.x + threadIdx.x;
    if (e < EE) {
        int c = col[e];
        atomicAdd(&g_deg[c], ea[e]);
        atomicAdd(&g_cnt[c], 1);
    }
}

__global__ void k_dinv() {
    int i = blockIdx.x * blockDim.x + threadIdx.x;
    if (i < NN) {
        float d = g_deg[i];
        g_dinv[i] = (d > 0.f) ? rsqrtf(d) : 0.f;
    }
}

__global__ void k_scan() {
    __shared__ int sh[1024];
    int tid = threadIdx.x;
    int carry = 0;
    for (int base = 0; base < NN; base += 1024) {
        int i = base + tid;
        int v = (i < NN) ? g_cnt[i] : 0;
        sh[tid] = v;
        __syncthreads();
        for (int ofs = 1; ofs < 1024; ofs <<= 1) {
            int t = (tid >= ofs) ? sh[tid - ofs] : 0;
            __syncthreads();
            sh[tid] += t;
            __syncthreads();
        }
        if (i < NN) g_off[i] = carry + sh[tid] - v;
        carry += sh[1023];
        __syncthreads();
    }
    if (tid == 0) g_off[NN] = carry;
}

__global__ void k_cursor() {
    int i = blockIdx.x * blockDim.x + threadIdx.x;
    if (i < NN) g_cur[i] = g_off[i];
}

__global__ void k_scatter(const int* __restrict__ row, const int* __restrict__ col,
                          const float* __restrict__ ea) {
    int e = blockIdx.x * blockDim.x + threadIdx.x;
    if (e < EE) {
        int r = row[e], c = col[e];
        int p = atomicAdd(&g_cur[c], 1);
        g_srcs[p] = r;
        g_wsrt[p] = g_dinv[r] * ea[e] * g_dinv[c];
    }
}

// ---------------- pos hops (3 channels, thread per node) ----------------
__global__ void k_prop3(float* __restrict__ dst, const float* __restrict__ src) {
    int j = blockIdx.x * blockDim.x + threadIdx.x;
    if (j >= NN) return;
    int beg = g_off[j], end = g_off[j + 1];
    float a0 = 0.f, a1 = 0.f, a2 = 0.f;
    for (int e = beg; e < end; e++) {
        int s = g_srcs[e];
        float w = g_wsrt[e];
        a0 += w * src[s * 3 + 0];
        a1 += w * src[s * 3 + 1];
        a2 += w * src[s * 3 + 2];
    }
    dst[j * 3 + 0] = a0; dst[j * 3 + 1] = a1; dst[j * 3 + 2] = a2;
}

// posacc[n,c] = sum_{k=0..3} sum_{j=0..2} ppk[n,j] * c1_w[k][64+j][c]
__global__ void k_posacc(const float* __restrict__ pos, const float* __restrict__ c1w) {
    int idx = blockIdx.x * blockDim.x + threadIdx.x;
    if (idx >= NN * HID) return;
    int n = idx >> 7, c = idx & 127;
    const float* pps[4] = {pos, g_pp1, g_pp2, g_pp3};
    float acc = 0.f;
#pragma unroll
    for (int k = 0; k < 4; k++) {
        const float* pp = pps[k] + n * 3;
        const float* wr = c1w + k * 67 * 128 + 64 * 128 + c;
        acc += pp[0] * wr[0] + pp[1] * wr[128] + pp[2] * wr[256];
    }
    g_posacc[idx] = acc;
}

// ---------------- up MLP: z0 = gelu(x@W1+b1)@W2+b2 ----------------
__global__ __launch_bounds__(256) void k_up(const float* __restrict__ x,
                                            const float* __restrict__ w1, const float* __restrict__ b1,
                                            const float* __restrict__ w2, const float* __restrict__ b2) {
    __shared__ float sw2[64 * 64];
    __shared__ float hid[4][64];
    int tid = threadIdx.x;
#pragma unroll
    for (int i = 0; i < 16; i++) sw2[tid * 16 + i] = w2[tid * 16 + i];
    int local = tid >> 6;
    int c = tid & 63;
    int node = blockIdx.x * 4 + local;
    float h = 0.f;
    if (node < NN) {
        h = b1[c];
#pragma unroll
        for (int i = 0; i < 4; i++) h += x[node * 4 + i] * w1[i * 64 + c];
        h = gelu_exact(h);
    }
    hid[local][c] = h;
    __syncthreads();
    if (node < NN) {
        float o = b2[c];
#pragma unroll
        for (int j = 0; j < 64; j++) o += hid[local][j] * sw2[j * 64 + c];
        g_z[node * 64 + c] = o;
    }
}

// ---------------- propagation kernels (CSR, warp per node) ----------------
__global__ __launch_bounds__(256) void k_prop64(float* __restrict__ dst, const float* __restrict__ src) {
    int wrp = threadIdx.x >> 5, lane = threadIdx.x & 31;
    int j = blockIdx.x * 8 + wrp;
    if (j >= NN) return;
    int beg = g_off[j], end = g_off[j + 1];
    float2 a0 = {0.f, 0.f}, a1 = {0.f, 0.f};
    int e = beg;
    for (; e + 2 <= end; e += 2) {
        int s0 = g_srcs[e], s1 = g_srcs[e + 1];
        float w0 = g_wsrt[e], w1 = g_wsrt[e + 1];
        float2 v0 = *(const float2*)(src + (size_t)s0 * 64 + lane * 2);
        float2 v1 = *(const float2*)(src + (size_t)s1 * 64 + lane * 2);
        a0.x = fmaf(w0, v0.x, a0.x); a0.y = fmaf(w0, v0.y, a0.y);
        a1.x = fmaf(w1, v1.x, a1.x); a1.y = fmaf(w1, v1.y, a1.y);
    }
    if (e < end) {
        int s0 = g_srcs[e];
        float w0 = g_wsrt[e];
        float2 v0 = *(const float2*)(src + (size_t)s0 * 64 + lane * 2);
        a0.x = fmaf(w0, v0.x, a0.x); a0.y = fmaf(w0, v0.y, a0.y);
    }
    float2 r; r.x = a0.x + a1.x; r.y = a0.y + a1.y;
    *(float2*)(dst + (size_t)j * 64 + lane * 2) = r;
}

__global__ __launch_bounds__(256) void k_prop128(float* __restrict__ dst, const float* __restrict__ src) {
    int wrp = threadIdx.x >> 5, lane = threadIdx.x & 31;
    int j = blockIdx.x * 8 + wrp;
    if (j >= NN) return;
    int beg = g_off[j], end = g_off[j + 1];
    float4 a0 = {0.f,0.f,0.f,0.f}, a1 = {0.f,0.f,0.f,0.f};
    int e = beg;
    for (; e + 2 <= end; e += 2) {
        int s0 = g_srcs[e], s1 = g_srcs[e + 1];
        float w0 = g_wsrt[e], w1 = g_wsrt[e + 1];
        float4 v0 = *(const float4*)(src + (size_t)s0 * 128 + lane * 4);
        float4 v1 = *(const float4*)(src + (size_t)s1 * 128 + lane * 4);
        a0.x = fmaf(w0, v0.x, a0.x); a0.y = fmaf(w0, v0.y, a0.y);
        a0.z = fmaf(w0, v0.z, a0.z); a0.w = fmaf(w0, v0.w, a0.w);
        a1.x = fmaf(w1, v1.x, a1.x); a1.y = fmaf(w1, v1.y, a1.y);
        a1.z = fmaf(w1, v1.z, a1.z); a1.w = fmaf(w1, v1.w, a1.w);
    }
    if (e < end) {
        int s0 = g_srcs[e];
        float w0 = g_wsrt[e];
        float4 v0 = *(const float4*)(src + (size_t)s0 * 128 + lane * 4);
        a0.x = fmaf(w0, v0.x, a0.x); a0.y = fmaf(w0, v0.y, a0.y);
        a0.z = fmaf(w0, v0.z, a0.z); a0.w = fmaf(w0, v0.w, a0.w);
    }
    float4 r;
    r.x = a0.x + a1.x; r.y = a0.y + a1.y; r.z = a0.z + a1.z; r.w = a0.w + a1.w;
    *(float4*)(dst + (size_t)j * 128 + lane * 4) = r;
}

// tag3: dst = P src + add   (64 channels)
__global__ __launch_bounds__(256) void k_propadd64(float* __restrict__ dst, const float* __restrict__ src,
                                                   const float* __restrict__ add) {
    int wrp = threadIdx.x >> 5, lane = threadIdx.x & 31;
    int j = blockIdx.x * 8 + wrp;
    if (j >= NN) return;
    int beg = g_off[j], end = g_off[j + 1];
    float2 a0 = {0.f, 0.f}, a1 = {0.f, 0.f};
    int e = beg;
    for (; e + 2 <= end; e += 2) {
        int s0 = g_srcs[e], s1 = g_srcs[e + 1];
        float w0 = g_wsrt[e], w1 = g_wsrt[e + 1];
        float2 v0 = *(const float2*)(src + (size_t)s0 * 64 + lane * 2);
        float2 v1 = *(const float2*)(src + (size_t)s1 * 64 + lane * 2);
        a0.x = fmaf(w0, v0.x, a0.x); a0.y = fmaf(w0, v0.y, a0.y);
        a1.x = fmaf(w1, v1.x, a1.x); a1.y = fmaf(w1, v1.y, a1.y);
    }
    if (e < end) {
        int s0 = g_srcs[e];
        float w0 = g_wsrt[e];
        float2 v0 = *(const float2*)(src + (size_t)s0 * 64 + lane * 2);
        a0.x = fmaf(w0, v0.x, a0.x); a0.y = fmaf(w0, v0.y, a0.y);
    }
    float2 ad = *(const float2*)(add + (size_t)j * 64 + lane * 2);
    float2 r; r.x = a0.x + a1.x + ad.x; r.y = a0.y + a1.y + ad.y;
    *(float2*)(dst + (size_t)j * 64 + lane * 2) = r;
}

// tag3 final: z = log_softmax(P src + add + bias)
__global__ __launch_bounds__(256) void k_proplogsm(const float* __restrict__ src,
                                                   const float* __restrict__ add,
                                                   const float* __restrict__ bias) {
    int wrp = threadIdx.x >> 5, lane = threadIdx.x & 31;
    int j = blockIdx.x * 8 + wrp;
    if (j >= NN) return;
    int beg = g_off[j], end = g_off[j + 1];
    float2 a0 = {0.f, 0.f}, a1 = {0.f, 0.f};
    int e = beg;
    for (; e + 2 <= end; e += 2) {
        int s0 = g_srcs[e], s1 = g_srcs[e + 1];
        float w0 = g_wsrt[e], w1 = g_wsrt[e + 1];
        float2 v0 = *(const float2*)(src + (size_t)s0 * 64 + lane * 2);
        float2 v1 = *(const float2*)(src + (size_t)s1 * 64 + lane * 2);
        a0.x = fmaf(w0, v0.x, a0.x); a0.y = fmaf(w0, v0.y, a0.y);
        a1.x = fmaf(w1, v1.x, a1.x); a1.y = fmaf(w1, v1.y, a1.y);
    }
    if (e < end) {
        int s0 = g_srcs[e];
        float w0 = g_wsrt[e];
        float2 v0 = *(const float2*)(src + (size_t)s0 * 64 + lane * 2);
        a0.x = fmaf(w0, v0.x, a0.x); a0.y = fmaf(w0, v0.y, a0.y);
    }
    float2 ad = *(const float2*)(add + (size_t)j * 64 + lane * 2);
    float v0 = a0.x + a1.x + ad.x + bias[2 * lane];
    float v1 = a0.y + a1.y + ad.y + bias[2 * lane + 1];
    float m = fmaxf(v0, v1);
#pragma unroll
    for (int o = 16; o; o >>= 1) m = fmaxf(m, __shfl_xor_sync(0xffffffffu, m, o));
    float s = expf(v0 - m) + expf(v1 - m);
#pragma unroll
    for (int o = 16; o; o >>= 1) s += __shfl_xor_sync(0xffffffffu, s, o);
    float l = m + logf(s);
    g_z[j * 64 + 2 * lane]     = v0 - l;
    g_z[j * 64 + 2 * lane + 1] = v1 - l;
}

// ---------------- fused 4-hop GEMM (scalar FFMA inner loop, COUT=128) -------------
// h = relu( sum_{k=0..3} A_k @ W_k  [+ addend] + bias )
// W_k = W + k*wstride, rows [CinH,128] row-major
template <int CinH, bool ADDEND>
__global__ __launch_bounds__(256) void k_gemm4(const float* __restrict__ A0, const float* __restrict__ A1,
                                               const float* __restrict__ A2, const float* __restrict__ A3,
                                               const float* __restrict__ W, size_t wstride,
                                               const float* __restrict__ addend,
                                               const float* __restrict__ bias,
                                               float* __restrict__ hdst) {
    __shared__ __align__(16) float As[16][64];
    __shared__ __align__(16) float Ws[16][128];
    int tid = threadIdx.x, lane = tid & 31, wrp = tid >> 5;
    int row0 = blockIdx.x * 64;
    int rb = wrp * 8;
    float acc[8][4];
#pragma unroll
    for (int r = 0; r < 8; r++)
#pragma unroll
        for (int c = 0; c < 4; c++) acc[r][c] = 0.f;

    int lr = tid >> 2;          // 0..63 A row in tile
    int lk = (tid & 3) * 4;     // 0,4,8,12
    int grow = row0 + lr;
    bool rowok = (grow < NN);
    const float* srcs[4] = {A0, A1, A2, A3};

#pragma unroll 1
    for (int hop = 0; hop < 4; hop++) {
        const float* arow = srcs[hop] + (size_t)grow * CinH;
        const float* Wk = W + hop * wstride;
#pragma unroll 1
        for (int k0 = 0; k0 < CinH; k0 += 16) {
#pragma unroll
            for (int i = 0; i < 4; i++) {
                int kk = lk + i;
                As[kk][lr] = rowok ? arow[k0 + kk] : 0.f;
            }
#pragma unroll
            for (int i = 0; i < 8; i++) {
                int off = tid * 8 + i;
                int kk = off >> 7, c = off & 127;
                Ws[kk][c] = Wk[(size_t)(k0 + kk) * 128 + c];
            }
            __syncthreads();
#pragma unroll
            for (int kk = 0; kk < 16; kk++) {
                float a[8];
                float4 a0 = *(const float4*)&As[kk][rb];
                float4 a1 = *(const float4*)&As[kk][rb + 4];
                a[0] = a0.x; a[1] = a0.y; a[2] = a0.z; a[3] = a0.w;
                a[4] = a1.x; a[5] = a1.y; a[6] = a1.z; a[7] = a1.w;
                float4 wv = *(const float4*)&Ws[kk][lane * 4];
                float w[4] = {wv.x, wv.y, wv.z, wv.w};
#pragma unroll
                for (int r = 0; r < 8; r++)
#pragma unroll
                    for (int c = 0; c < 4; c++)
                        acc[r][c] = fmaf(a[r], w[c], acc[r][c]);
            }
            __syncthreads();
        }
    }

    float4 bv = *(const float4*)&bias[lane * 4];
    float bb[4] = {bv.x, bv.y, bv.z, bv.w};
#pragma unroll
    for (int r = 0; r < 8; r++) {
        int row = row0 + rb + r;
        if (row < NN) {
            size_t base = (size_t)row * 128 + lane * 4;
            float v[4];
            if constexpr (ADDEND) {
                float4 ad = *(const float4*)&addend[base];
                v[0] = acc[r][0] + ad.x; v[1] = acc[r][1] + ad.y;
                v[2] = acc[r][2] + ad.z; v[3] = acc[r][3] + ad.w;
            } else {
                v[0] = acc[r][0]; v[1] = acc[r][1]; v[2] = acc[r][2]; v[3] = acc[r][3];
            }
            float4 o;
            o.x = fmaxf(v[0] + bb[0], 0.f);
            o.y = fmaxf(v[1] + bb[1], 0.f);
            o.z = fmaxf(v[2] + bb[2], 0.f);
            o.w = fmaxf(v[3] + bb[3], 0.f);
            *(float4*)(hdst + base) = o;
        }
    }
}

// ---------------- paired GEMM: out0 = A@W0, out1 = A@W1 (A [N,128], W [128,64]) ----
__global__ __launch_bounds__(256) void k_gemm_pair(const float* __restrict__ A,
                                                   const float* __restrict__ W0, const float* __restrict__ W1,
                                                   float* __restrict__ out0, float* __restrict__ out1) {
    __shared__ __align__(16) float As[16][64];
    __shared__ __align__(16) float Ws[16][128];
    int tid = threadIdx.x, lane = tid & 31, wrp = tid >> 5;
    int row0 = blockIdx.x * 64;
    int rb = wrp * 8;
    float acc[8][4];
#pragma unroll
    for (int r = 0; r < 8; r++)
#pragma unroll
        for (int c = 0; c < 4; c++) acc[r][c] = 0.f;

    int lr = tid >> 2;
    int lk = (tid & 3) * 4;
    int grow = row0 + lr;
    bool rowok = (grow < NN);
    const float* arow = A + (size_t)grow * 128;

#pragma unroll 1
    for (int k0 = 0; k0 < 128; k0 += 16) {
#pragma unroll
        for (int i = 0; i < 4; i++) {
            int kk = lk + i;
            As[kk][lr] = rowok ? arow[k0 + kk] : 0.f;
        }
#pragma unroll
        for (int i = 0; i < 8; i++) {
            int off = tid * 8 + i;
            int kk = off >> 7, c = off & 127;
            const float* Wp = (c < 64) ? W0 : W1;
            Ws[kk][c] = Wp[(size_t)(k0 + kk) * 64 + (c & 63)];
        }
        __syncthreads();
#pragma unroll
        for (int kk = 0; kk < 16; kk++) {
            float a[8];
            float4 a0 = *(const float4*)&As[kk][rb];
            float4 a1 = *(const float4*)&As[kk][rb + 4];
            a[0] = a0.x; a[1] = a0.y; a[2] = a0.z; a[3] = a0.w;
            a[4] = a1.x; a[5] = a1.y; a[6] = a1.z; a[7] = a1.w;
            float4 wv = *(const float4*)&Ws[kk][lane * 4];
            float w[4] = {wv.x, wv.y, wv.z, wv.w};
#pragma unroll
            for (int r = 0; r < 8; r++)
#pragma unroll
                for (int c = 0; c < 4; c++)
                    acc[r][c] = fmaf(a[r], w[c], acc[r][c]);
        }
        __syncthreads();
    }

    // lanes 0..15 -> out0 couts (lane*4), lanes 16..31 -> out1 couts ((lane-16)*4)
    float* outp = (lane < 16) ? out0 : out1;
    int cl = (lane & 15) * 4;
#pragma unroll
    for (int r = 0; r < 8; r++) {
        int row = row0 + rb + r;
        if (row < NN) {
            float4 v; v.x = acc[r][0]; v.y = acc[r][1]; v.z = acc[r][2]; v.w = acc[r][3];
            *(float4*)(outp + (size_t)row * 64 + cl) = v;
        }
    }
}

// ---------------- down MLP + output write ----------------
__global__ __launch_bounds__(256) void k_down(float* __restrict__ out,
                                              const float* __restrict__ w1, const float* __restrict__ b1,
                                              const float* __restrict__ w2, const float* __restrict__ b2) {
    int wrp = threadIdx.x >> 5, lane = threadIdx.x & 31;
    int j = blockIdx.x * 8 + wrp;
    if (j >= NN) return;
    float z0 = g_z[j * 64 + lane];
    float z1 = g_z[j * 64 + 32 + lane];
    out[NN + j * 64 + lane] = z0;
    out[NN + j * 64 + 32 + lane] = z1;
    float d = z0 * w1[lane] + z1 * w1[32 + lane];
#pragma unroll
    for (int o = 16; o; o >>= 1) d += __shfl_xor_sync(0xffffffffu, d, o);
    if (lane == 0) out[j] = gelu_exact(d + b1[0]) * w2[0] + b2[0];
}

// ---------------- host orchestration ----------------
extern "C" void kernel_launch(void* const* d_in, const int* in_sizes, int n_in,
                              void* d_out, int out_size) {
    const float* x      = (const float*)d_in[0];
    const float* pos    = (const float*)d_in[1];
    const float* ea     = (const float*)d_in[2];
    const float* up_w1  = (const float*)d_in[3];
    const float* up_b1  = (const float*)d_in[4];
    const float* up_w2  = (const float*)d_in[5];
    const float* up_b2  = (const float*)d_in[6];
    const float* c1_w   = (const float*)d_in[7];
    const float* c1_b   = (const float*)d_in[8];
    const float* c2_w   = (const float*)d_in[9];
    const float* c2_b   = (const float*)d_in[10];
    const float* c3_w   = (const float*)d_in[11];
    const float* c3_b   = (const float*)d_in[12];
    const float* dw1    = (const float*)d_in[13];
    const float* db1    = (const float*)d_in[14];
    const float* dw2    = (const float*)d_in[15];
    const float* db2    = (const float*)d_in[16];
    const int*   ei     = (const int*)d_in[17];
    const int* row = ei;
    const int* col = ei + EE;

    float *z, *h, *p1, *p2, *p3, *y0, *y1, *y2, *y3, *pp1, *pp2, *pp3, *posacc;
    cudaGetSymbolAddress((void**)&z,      g_z);
    cudaGetSymbolAddress((void**)&h,      g_h);
    cudaGetSymbolAddress((void**)&p1,     g_p1);
    cudaGetSymbolAddress((void**)&p2,     g_p2);
    cudaGetSymbolAddress((void**)&p3,     g_p3);
    cudaGetSymbolAddress((void**)&y0,     g_y0);
    cudaGetSymbolAddress((void**)&y1,     g_y1);
    cudaGetSymbolAddress((void**)&y2,     g_y2);
    cudaGetSymbolAddress((void**)&y3,     g_y3);
    cudaGetSymbolAddress((void**)&pp1,    g_pp1);
    cudaGetSymbolAddress((void**)&pp2,    g_pp2);
    cudaGetSymbolAddress((void**)&pp3,    g_pp3);
    cudaGetSymbolAddress((void**)&posacc, g_posacc);

    const int GN = (NN + 255) / 256;
    const int GE = (EE + 255) / 256;
    const int GW = (NN + 7) / 8;       // warp-per-node grids
    const int GG = (NN + 63) / 64;     // gemm grids
    const int GP = (NN * HID + 255) / 256;

    // --- graph setup (CSR by destination, gcn norm) ---
    k_zero<<<GN, 256>>>();
    k_hist<<<GE, 256>>>(col, ea);
    k_dinv<<<GN, 256>>>();
    k_scan<<<1, 1024>>>();
    k_cursor<<<GN, 256>>>();
    k_scatter<<<GE, 256>>>(row, col, ea);

    // --- iteration-invariant pos hops + pos contribution to tag1 ---
    k_prop3<<<GN, 256>>>(pp1, pos);
    k_prop3<<<GN, 256>>>(pp2, pp1);
    k_prop3<<<GN, 256>>>(pp3, pp2);
    k_posacc<<<GP, 256>>>(pos, c1_w);

    // --- up MLP -> z0 ---
    k_up<<<(NN + 3) / 4, 256>>>(x, up_w1, up_b1, up_w2, up_b2);

    const size_t W1S = 67 * 128;     // c1_w per-k stride (z-part = first 64 rows)
    const size_t W2S = 128 * 128;
    const size_t W3S = 128 * 64;

    // --- 21 gnn applications (20 fixed-point + 1 phantom) ---
    for (int it = 0; it < 21; it++) {
        // tag1: hops on z (64ch), fused GEMM -> h (relu, +posacc)
        k_prop64<<<GW, 256>>>(p1, z);
        k_prop64<<<GW, 256>>>(p2, p1);
        k_prop64<<<GW, 256>>>(p3, p2);
        k_gemm4<64, true><<<GG, 256>>>(z, p1, p2, p3, c1_w, W1S, posacc, c1_b, h);

        // tag2: hops on h (128ch), fused GEMM -> h (relu)
        k_prop128<<<GW, 256>>>(p1, h);
        k_prop128<<<GW, 256>>>(p2, p1);
        k_prop128<<<GW, 256>>>(p3, p2);
        k_gemm4<128, false><<<GG, 256>>>(h, p1, p2, p3, c2_w, W2S, nullptr, c2_b, h);

        // tag3: GEMMs first (prop commutes with channel map), then 64ch prop chain
        k_gemm_pair<<<GG, 256>>>(h, c3_w,           c3_w + 1 * W3S, y0, y1);
        k_gemm_pair<<<GG, 256>>>(h, c3_w + 2 * W3S, c3_w + 3 * W3S, y2, y3);
        k_propadd64<<<GW, 256>>>(p1, y3, y2);     // t1 = P y3 + y2
        k_propadd64<<<GW, 256>>>(p2, p1, y1);     // t2 = P t1 + y1
        k_proplogsm<<<GW, 256>>>(p2, y0, c3_b);   // z = logsm(P t2 + y0 + b)
    }

    // --- down MLP + write (out, z_star) ---
    k_down<<<GW, 256>>>((float*)d_out, dw1, db1, dw2, db2);

    (void)in_sizes; (void)n_in; (void)out_size;
}

// round 8
// speedup vs baseline: 1.9779x; 1.3561x over previous
#include <cuda_runtime.h>
#include <cuda_bf16.h>
#include <math.h>
#include <stdint.h>

#define NN 50000
#define EE 800000
#define EMB 64
#define HID 128

// ---------------- scratch (device globals; no allocation allowed) ----------------
__device__ float g_deg[NN];
__device__ float g_dinv[NN];
__device__ int   g_cnt[NN];
__device__ int   g_off[NN + 1];
__device__ int   g_cur[NN];
__device__ int   g_srcs[EE];
__device__ float g_wsrt[EE];

__device__ __align__(16) float g_z[NN * EMB];       // state z
__device__ __align__(16) float g_h[NN * HID];       // tag output (relu'd)
__device__ __align__(16) float g_p1[NN * HID];      // hop buffers
__device__ __align__(16) float g_p2[NN * HID];
__device__ __align__(16) float g_p3[NN * HID];
__device__ __align__(16) float g_y0[NN * EMB];      // tag3 per-k GEMM outputs
__device__ __align__(16) float g_y1[NN * EMB];
__device__ __align__(16) float g_y2[NN * EMB];
__device__ __align__(16) float g_y3[NN * EMB];
__device__ __align__(16) float g_pp1[NN * 3];
__device__ __align__(16) float g_pp2[NN * 3];
__device__ __align__(16) float g_pp3[NN * 3];
__device__ __align__(16) float g_posacc[NN * HID];

// pre-split, pre-transposed weights: [hop][s=hi/lo][n(128)][k(CINH)] bf16
__device__ __align__(16) __nv_bfloat16 g_wt1[4 * 2 * 128 * 64];
__device__ __align__(16) __nv_bfloat16 g_wt2[4 * 2 * 128 * 128];
__device__ __align__(16) __nv_bfloat16 g_wt3[2 * 2 * 128 * 128];

__device__ __forceinline__ float gelu_exact(float x) {
    return 0.5f * x * (1.0f + erff(x * 0.70710678118654752f));
}

// ---------------- mma.sync helper (bf16, m16n8k16, fp32 acc) ----------------
__device__ __forceinline__ void mma16816(float* d, const uint32_t* a, uint32_t b0, uint32_t b1) {
    asm volatile(
        "mma.sync.aligned.m16n8k16.row.col.f32.bf16.bf16.f32 "
        "{%0,%1,%2,%3}, {%4,%5,%6,%7}, {%8,%9}, {%0,%1,%2,%3};"
        : "+f"(d[0]), "+f"(d[1]), "+f"(d[2]), "+f"(d[3])
        : "r"(a[0]), "r"(a[1]), "r"(a[2]), "r"(a[3]), "r"(b0), "r"(b1));
}

// ---------------- setup kernels ----------------
__global__ void k_zero() {
    int i = blockIdx.x * blockDim.x + threadIdx.x;
    if (i < NN) { g_deg[i] = 0.f; g_cnt[i] = 0; }
}

__global__ void k_hist(const int* __restrict__ col, const float* __restrict__ ea) {
    int e = blockIdx.x * blockDim.x + threadIdx.x;
    if (e < EE) {
        int c = col[e];
        atomicAdd(&g_deg[c], ea[e]);
        atomicAdd(&g_cnt[c], 1);
    }
}

__global__ void k_dinv() {
    int i = blockIdx.x * blockDim.x + threadIdx.x;
    if (i < NN) {
        float d = g_deg[i];
        g_dinv[i] = (d > 0.f) ? rsqrtf(d) : 0.f;
    }
}

__global__ void k_scan() {
    __shared__ int sh[1024];
    int tid = threadIdx.x;
    int carry = 0;
    for (int base = 0; base < NN; base += 1024) {
        int i = base + tid;
        int v = (i < NN) ? g_cnt[i] : 0;
        sh[tid] = v;
        __syncthreads();
        for (int ofs = 1; ofs < 1024; ofs <<= 1) {
            int t = (tid >= ofs) ? sh[tid - ofs] : 0;
            __syncthreads();
            sh[tid] += t;
            __syncthreads();
        }
        if (i < NN) g_off[i] = carry + sh[tid] - v;
        carry += sh[1023];
        __syncthreads();
    }
    if (tid == 0) g_off[NN] = carry;
}

__global__ void k_cursor() {
    int i = blockIdx.x * blockDim.x + threadIdx.x;
    if (i < NN) g_cur[i] = g_off[i];
}

__global__ void k_scatter(const int* __restrict__ row, const int* __restrict__ col,
                          const float* __restrict__ ea) {
    int e = blockIdx.x * blockDim.x + threadIdx.x;
    if (e < EE) {
        int r = row[e], c = col[e];
        int p = atomicAdd(&g_cur[c], 1);
        g_srcs[p] = r;
        g_wsrt[p] = g_dinv[r] * ea[e] * g_dinv[c];
    }
}

// ---------------- weight prep: transpose + bf16 hi/lo split ----------------
__device__ __forceinline__ void split_store(__nv_bfloat16* hi, __nv_bfloat16* lo, float w) {
    __nv_bfloat16 hb = __float2bfloat16(w);
    *hi = hb;
    *lo = __float2bfloat16(w - __bfloat162float(hb));
}

__global__ void k_wprep1(const float* __restrict__ c1w) {   // [4][67][128] -> g_wt1 [4][2][128][64]
    int idx = blockIdx.x * blockDim.x + threadIdx.x;
    if (idx >= 4 * 128 * 64) return;
    int hop = idx / (128 * 64);
    int r = idx - hop * 128 * 64;
    int n = r >> 6, k = r & 63;
    float w = c1w[hop * 67 * 128 + k * 128 + n];
    size_t b = ((size_t)(hop * 2) * 128 + n) * 64 + k;
    split_store(&g_wt1[b], &g_wt1[b + 128 * 64], w);
}

__global__ void k_wprep2(const float* __restrict__ c2w) {   // [4][128][128] -> g_wt2 [4][2][128][128]
    int idx = blockIdx.x * blockDim.x + threadIdx.x;
    if (idx >= 4 * 128 * 128) return;
    int hop = idx / (128 * 128);
    int r = idx - hop * 128 * 128;
    int n = r >> 7, k = r & 127;
    float w = c2w[hop * 128 * 128 + k * 128 + n];
    size_t b = ((size_t)(hop * 2) * 128 + n) * 128 + k;
    split_store(&g_wt2[b], &g_wt2[b + 128 * 128], w);
}

__global__ void k_wprep3(const float* __restrict__ c3w) {   // [4][128][64] -> g_wt3 [2 pairs][2][128][128]
    int idx = blockIdx.x * blockDim.x + threadIdx.x;
    if (idx >= 2 * 128 * 128) return;
    int pair = idx / (128 * 128);
    int r = idx - pair * 128 * 128;
    int n = r >> 7, k = r & 127;
    int wk = pair * 2 + (n >> 6);
    int nn = n & 63;
    float w = c3w[wk * 128 * 64 + k * 64 + nn];
    size_t b = ((size_t)(pair * 2) * 128 + n) * 128 + k;
    split_store(&g_wt3[b], &g_wt3[b + 128 * 128], w);
}

// ---------------- pos hops + posacc ----------------
__global__ void k_prop3(float* __restrict__ dst, const float* __restrict__ src) {
    int j = blockIdx.x * blockDim.x + threadIdx.x;
    if (j >= NN) return;
    int beg = g_off[j], end = g_off[j + 1];
    float a0 = 0.f, a1 = 0.f, a2 = 0.f;
    for (int e = beg; e < end; e++) {
        int s = g_srcs[e];
        float w = g_wsrt[e];
        a0 += w * src[s * 3 + 0];
        a1 += w * src[s * 3 + 1];
        a2 += w * src[s * 3 + 2];
    }
    dst[j * 3 + 0] = a0; dst[j * 3 + 1] = a1; dst[j * 3 + 2] = a2;
}

__global__ void k_posacc(const float* __restrict__ pos, const float* __restrict__ c1w) {
    int idx = blockIdx.x * blockDim.x + threadIdx.x;
    if (idx >= NN * HID) return;
    int n = idx >> 7, c = idx & 127;
    const float* pps[4] = {pos, g_pp1, g_pp2, g_pp3};
    float acc = 0.f;
#pragma unroll
    for (int k = 0; k < 4; k++) {
        const float* pp = pps[k] + n * 3;
        const float* wr = c1w + k * 67 * 128 + 64 * 128 + c;
        acc += pp[0] * wr[0] + pp[1] * wr[128] + pp[2] * wr[256];
    }
    g_posacc[idx] = acc;
}

// ---------------- up MLP ----------------
__global__ __launch_bounds__(256) void k_up(const float* __restrict__ x,
                                            const float* __restrict__ w1, const float* __restrict__ b1,
                                            const float* __restrict__ w2, const float* __restrict__ b2) {
    __shared__ float sw2[64 * 64];
    __shared__ float hid[4][64];
    int tid = threadIdx.x;
#pragma unroll
    for (int i = 0; i < 16; i++) sw2[tid * 16 + i] = w2[tid * 16 + i];
    int local = tid >> 6;
    int c = tid & 63;
    int node = blockIdx.x * 4 + local;
    float h = 0.f;
    if (node < NN) {
        h = b1[c];
#pragma unroll
        for (int i = 0; i < 4; i++) h += x[node * 4 + i] * w1[i * 64 + c];
        h = gelu_exact(h);
    }
    hid[local][c] = h;
    __syncthreads();
    if (node < NN) {
        float o = b2[c];
#pragma unroll
        for (int j = 0; j < 64; j++) o += hid[local][j] * sw2[j * 64 + c];
        g_z[node * 64 + c] = o;
    }
}

// ---------------- propagation kernels (CSR, warp per node) ----------------
__global__ __launch_bounds__(256) void k_prop64(float* __restrict__ dst, const float* __restrict__ src) {
    int wrp = threadIdx.x >> 5, lane = threadIdx.x & 31;
    int j = blockIdx.x * 8 + wrp;
    if (j >= NN) return;
    int beg = g_off[j], end = g_off[j + 1];
    float2 a0 = {0.f, 0.f}, a1 = {0.f, 0.f};
    int e = beg;
    for (; e + 2 <= end; e += 2) {
        int s0 = g_srcs[e], s1 = g_srcs[e + 1];
        float w0 = g_wsrt[e], w1 = g_wsrt[e + 1];
        float2 v0 = *(const float2*)(src + (size_t)s0 * 64 + lane * 2);
        float2 v1 = *(const float2*)(src + (size_t)s1 * 64 + lane * 2);
        a0.x = fmaf(w0, v0.x, a0.x); a0.y = fmaf(w0, v0.y, a0.y);
        a1.x = fmaf(w1, v1.x, a1.x); a1.y = fmaf(w1, v1.y, a1.y);
    }
    if (e < end) {
        int s0 = g_srcs[e];
        float w0 = g_wsrt[e];
        float2 v0 = *(const float2*)(src + (size_t)s0 * 64 + lane * 2);
        a0.x = fmaf(w0, v0.x, a0.x); a0.y = fmaf(w0, v0.y, a0.y);
    }
    float2 r; r.x = a0.x + a1.x; r.y = a0.y + a1.y;
    *(float2*)(dst + (size_t)j * 64 + lane * 2) = r;
}

__global__ __launch_bounds__(256) void k_prop128(float* __restrict__ dst, const float* __restrict__ src) {
    int wrp = threadIdx.x >> 5, lane = threadIdx.x & 31;
    int j = blockIdx.x * 8 + wrp;
    if (j >= NN) return;
    int beg = g_off[j], end = g_off[j + 1];
    float4 a0 = {0.f,0.f,0.f,0.f}, a1 = {0.f,0.f,0.f,0.f};
    int e = beg;
    for (; e + 2 <= end; e += 2) {
        int s0 = g_srcs[e], s1 = g_srcs[e + 1];
        float w0 = g_wsrt[e], w1 = g_wsrt[e + 1];
        float4 v0 = *(const float4*)(src + (size_t)s0 * 128 + lane * 4);
        float4 v1 = *(const float4*)(src + (size_t)s1 * 128 + lane * 4);
        a0.x = fmaf(w0, v0.x, a0.x); a0.y = fmaf(w0, v0.y, a0.y);
        a0.z = fmaf(w0, v0.z, a0.z); a0.w = fmaf(w0, v0.w, a0.w);
        a1.x = fmaf(w1, v1.x, a1.x); a1.y = fmaf(w1, v1.y, a1.y);
        a1.z = fmaf(w1, v1.z, a1.z); a1.w = fmaf(w1, v1.w, a1.w);
    }
    if (e < end) {
        int s0 = g_srcs[e];
        float w0 = g_wsrt[e];
        float4 v0 = *(const float4*)(src + (size_t)s0 * 128 + lane * 4);
        a0.x = fmaf(w0, v0.x, a0.x); a0.y = fmaf(w0, v0.y, a0.y);
        a0.z = fmaf(w0, v0.z, a0.z); a0.w = fmaf(w0, v0.w, a0.w);
    }
    float4 r;
    r.x = a0.x + a1.x; r.y = a0.y + a1.y; r.z = a0.z + a1.z; r.w = a0.w + a1.w;
    *(float4*)(dst + (size_t)j * 128 + lane * 4) = r;
}

__global__ __launch_bounds__(256) void k_propadd64(float* __restrict__ dst, const float* __restrict__ src,
                                                   const float* __restrict__ add) {
    int wrp = threadIdx.x >> 5, lane = threadIdx.x & 31;
    int j = blockIdx.x * 8 + wrp;
    if (j >= NN) return;
    int beg = g_off[j], end = g_off[j + 1];
    float2 a0 = {0.f, 0.f}, a1 = {0.f, 0.f};
    int e = beg;
    for (; e + 2 <= end; e += 2) {
        int s0 = g_srcs[e], s1 = g_srcs[e + 1];
        float w0 = g_wsrt[e], w1 = g_wsrt[e + 1];
        float2 v0 = *(const float2*)(src + (size_t)s0 * 64 + lane * 2);
        float2 v1 = *(const float2*)(src + (size_t)s1 * 64 + lane * 2);
        a0.x = fmaf(w0, v0.x, a0.x); a0.y = fmaf(w0, v0.y, a0.y);
        a1.x = fmaf(w1, v1.x, a1.x); a1.y = fmaf(w1, v1.y, a1.y);
    }
    if (e < end) {
        int s0 = g_srcs[e];
        float w0 = g_wsrt[e];
        float2 v0 = *(const float2*)(src + (size_t)s0 * 64 + lane * 2);
        a0.x = fmaf(w0, v0.x, a0.x); a0.y = fmaf(w0, v0.y, a0.y);
    }
    float2 ad = *(const float2*)(add + (size_t)j * 64 + lane * 2);
    float2 r; r.x = a0.x + a1.x + ad.x; r.y = a0.y + a1.y + ad.y;
    *(float2*)(dst + (size_t)j * 64 + lane * 2) = r;
}

__global__ __launch_bounds__(256) void k_proplogsm(const float* __restrict__ src,
                                                   const float* __restrict__ add,
                                                   const float* __restrict__ bias) {
    int wrp = threadIdx.x >> 5, lane = threadIdx.x & 31;
    int j = blockIdx.x * 8 + wrp;
    if (j >= NN) return;
    int beg = g_off[j], end = g_off[j + 1];
    float2 a0 = {0.f, 0.f}, a1 = {0.f, 0.f};
    int e = beg;
    for (; e + 2 <= end; e += 2) {
        int s0 = g_srcs[e], s1 = g_srcs[e + 1];
        float w0 = g_wsrt[e], w1 = g_wsrt[e + 1];
        float2 v0 = *(const float2*)(src + (size_t)s0 * 64 + lane * 2);
        float2 v1 = *(const float2*)(src + (size_t)s1 * 64 + lane * 2);
        a0.x = fmaf(w0, v0.x, a0.x); a0.y = fmaf(w0, v0.y, a0.y);
        a1.x = fmaf(w1, v1.x, a1.x); a1.y = fmaf(w1, v1.y, a1.y);
    }
    if (e < end) {
        int s0 = g_srcs[e];
        float w0 = g_wsrt[e];
        float2 v0 = *(const float2*)(src + (size_t)s0 * 64 + lane * 2);
        a0.x = fmaf(w0, v0.x, a0.x); a0.y = fmaf(w0, v0.y, a0.y);
    }
    float2 ad = *(const float2*)(add + (size_t)j * 64 + lane * 2);
    float v0 = a0.x + a1.x + ad.x + bias[2 * lane];
    float v1 = a0.y + a1.y + ad.y + bias[2 * lane + 1];
    float m = fmaxf(v0, v1);
#pragma unroll
    for (int o = 16; o; o >>= 1) m = fmaxf(m, __shfl_xor_sync(0xffffffffu, m, o));
    float s = expf(v0 - m) + expf(v1 - m);
#pragma unroll
    for (int o = 16; o; o >>= 1) s += __shfl_xor_sync(0xffffffffu, s, o);
    float l = m + logf(s);
    g_z[j * 64 + 2 * lane]     = v0 - l;
    g_z[j * 64 + 2 * lane + 1] = v1 - l;
}

// ---------------- tensor GEMM via mma.sync (bf16 2-term split, fp32 acc) -----------
// D[128 rows, 128 cols] = sum_{hop} A_hop[rows, CINH] @ Wt_hop^T
// MODE 0: out0[row*128+c] = relu(D + addend? + bias)
// MODE 1: out0[row*64+c] (c<64), out1[row*64+(c-64)] (c>=64), raw
template <int CINH, int NHOPS, int MODE>
__global__ __launch_bounds__(256)
void k_mma(const float* __restrict__ A0, const float* __restrict__ A1,
           const float* __restrict__ A2, const float* __restrict__ A3,
           const __nv_bfloat16* __restrict__ Wt,
           const float* __restrict__ addend, const float* __restrict__ bias,
           float* __restrict__ out0, float* __restrict__ out1) {
    constexpr int ASTR = CINH + 8;   // padded stride (bf16 elems); 16B mod 128B -> conflict-free frags
    extern __shared__ __align__(16) char sm[];
    __nv_bfloat16* sAhi = (__nv_bfloat16*)sm;
    __nv_bfloat16* sAlo = sAhi + 128 * ASTR;
    __nv_bfloat16* sWhi = sAlo + 128 * ASTR;
    __nv_bfloat16* sWlo = sWhi + 128 * ASTR;

    int tid = threadIdx.x, wid = tid >> 5, lane = tid & 31;
    int wm = wid & 3, wn = wid >> 2;       // 4 m-tiles x 2 n-tiles of warps
    int grp = lane >> 2, tig = lane & 3;

    float acc[2][8][4];
#pragma unroll
    for (int i = 0; i < 2; i++)
#pragma unroll
        for (int j = 0; j < 8; j++)
#pragma unroll
            for (int q = 0; q < 4; q++) acc[i][j][q] = 0.f;

    const float* As[4] = {A0, A1, A2, A3};
    int row0 = blockIdx.x * 128;
    constexpr int KQ4 = CINH / 4;
    constexpr int KQ8 = CINH / 8;

    for (int h = 0; h < NHOPS; h++) {
        if (h) __syncthreads();
        // --- fill A (fp32 -> bf16 hi/lo) ---
        const float* Ah = As[h];
        for (int u = tid; u < 128 * KQ4; u += 256) {
            int r = u / KQ4;
            int k4 = (u - r * KQ4) * 4;
            int grow = row0 + r;
            float4 f;
            if (grow < NN) f = *(const float4*)(Ah + (size_t)grow * CINH + k4);
            else { f.x = f.y = f.z = f.w = 0.f; }
            float v[4] = {f.x, f.y, f.z, f.w};
            uint32_t hp[2], lp[2];
#pragma unroll
            for (int i = 0; i < 2; i++) {
                __nv_bfloat16 h0 = __float2bfloat16(v[2 * i]);
                __nv_bfloat16 h1 = __float2bfloat16(v[2 * i + 1]);
                __nv_bfloat16 l0 = __float2bfloat16(v[2 * i] - __bfloat162float(h0));
                __nv_bfloat16 l1 = __float2bfloat16(v[2 * i + 1] - __bfloat162float(h1));
                hp[i] = (uint32_t)__bfloat16_as_ushort(h0) | ((uint32_t)__bfloat16_as_ushort(h1) << 16);
                lp[i] = (uint32_t)__bfloat16_as_ushort(l0) | ((uint32_t)__bfloat16_as_ushort(l1) << 16);
            }
            *(uint2*)(sAhi + r * ASTR + k4) = make_uint2(hp[0], hp[1]);
            *(uint2*)(sAlo + r * ASTR + k4) = make_uint2(lp[0], lp[1]);
        }
        // --- fill W (bf16 copy) ---
        for (int u = tid; u < 2 * 128 * KQ8; u += 256) {
            int s = u / (128 * KQ8);
            int rem = u - s * 128 * KQ8;
            int n = rem / KQ8;
            int k8 = (rem - n * KQ8) * 8;
            uint4 vv = *(const uint4*)(Wt + ((size_t)((h * 2 + s) * 128 + n)) * CINH + k8);
            *(uint4*)((s ? sWlo : sWhi) + n * ASTR + k8) = vv;
        }
        __syncthreads();

        // --- 3 split passes over full K ---
#pragma unroll
        for (int pass = 0; pass < 3; pass++) {
            const __nv_bfloat16* Ab = (pass == 2) ? sAlo : sAhi;
            const __nv_bfloat16* Wb = (pass == 1) ? sWlo : sWhi;
#pragma unroll
            for (int k8 = 0; k8 < CINH / 16; k8++) {
                uint32_t a[2][4];
                const __nv_bfloat16* ab = Ab + (wm * 32 + grp) * ASTR + k8 * 16 + 2 * tig;
#pragma unroll
                for (int ms = 0; ms < 2; ms++) {
                    const __nv_bfloat16* p = ab + ms * 16 * ASTR;
                    a[ms][0] = *(const uint32_t*)p;
                    a[ms][1] = *(const uint32_t*)(p + 8 * ASTR);
                    a[ms][2] = *(const uint32_t*)(p + 8);
                    a[ms][3] = *(const uint32_t*)(p + 8 * ASTR + 8);
                }
                const __nv_bfloat16* bb = Wb + (wn * 64 + grp) * ASTR + k8 * 16 + 2 * tig;
#pragma unroll
                for (int n8 = 0; n8 < 8; n8++) {
                    uint32_t b0 = *(const uint32_t*)(bb + n8 * 8 * ASTR);
                    uint32_t b1 = *(const uint32_t*)(bb + n8 * 8 * ASTR + 8);
                    mma16816(acc[0][n8], a[0], b0, b1);
                    mma16816(acc[1][n8], a[1], b0, b1);
                }
            }
        }
    }

    // --- epilogue ---
#pragma unroll
    for (int ms = 0; ms < 2; ms++) {
        int r0 = row0 + wm * 32 + ms * 16 + grp;
        int r1 = r0 + 8;
#pragma unroll
        for (int n8 = 0; n8 < 8; n8++) {
            int cb = wn * 64 + n8 * 8 + 2 * tig;
            float* d = acc[ms][n8];
            if constexpr (MODE == 0) {
                float b0v = __ldg(bias + cb), b1v = __ldg(bias + cb + 1);
                if (r0 < NN) {
                    float v0 = d[0] + b0v, v1 = d[1] + b1v;
                    if (addend) {
                        float2 ad = *(const float2*)(addend + (size_t)r0 * 128 + cb);
                        v0 += ad.x; v1 += ad.y;
                    }
                    float2 o; o.x = fmaxf(v0, 0.f); o.y = fmaxf(v1, 0.f);
                    *(float2*)(out0 + (size_t)r0 * 128 + cb) = o;
                }
                if (r1 < NN) {
                    float v0 = d[2] + b0v, v1 = d[3] + b1v;
                    if (addend) {
                        float2 ad = *(const float2*)(addend + (size_t)r1 * 128 + cb);
                        v0 += ad.x; v1 += ad.y;
                    }
                    float2 o; o.x = fmaxf(v0, 0.f); o.y = fmaxf(v1, 0.f);
                    *(float2*)(out0 + (size_t)r1 * 128 + cb) = o;
                }
            } else {
                float* op = wn ? out1 : out0;
                int cc = n8 * 8 + 2 * tig;
                if (r0 < NN) {
                    float2 o; o.x = d[0]; o.y = d[1];
                    *(float2*)(op + (size_t)r0 * 64 + cc) = o;
                }
                if (r1 < NN) {
                    float2 o; o.x = d[2]; o.y = d[3];
                    *(float2*)(op + (size_t)r1 * 64 + cc) = o;
                }
            }
        }
    }
}

// ---------------- down MLP + output write ----------------
__global__ __launch_bounds__(256) void k_down(float* __restrict__ out,
                                              const float* __restrict__ w1, const float* __restrict__ b1,
                                              const float* __restrict__ w2, const float* __restrict__ b2) {
    int wrp = threadIdx.x >> 5, lane = threadIdx.x & 31;
    int j = blockIdx.x * 8 + wrp;
    if (j >= NN) return;
    float z0 = g_z[j * 64 + lane];
    float z1 = g_z[j * 64 + 32 + lane];
    out[NN + j * 64 + lane] = z0;
    out[NN + j * 64 + 32 + lane] = z1;
    float d = z0 * w1[lane] + z1 * w1[32 + lane];
#pragma unroll
    for (int o = 16; o; o >>= 1) d += __shfl_xor_sync(0xffffffffu, d, o);
    if (lane == 0) out[j] = gelu_exact(d + b1[0]) * w2[0] + b2[0];
}

// ---------------- host orchestration ----------------
extern "C" void kernel_launch(void* const* d_in, const int* in_sizes, int n_in,
                              void* d_out, int out_size) {
    const float* x      = (const float*)d_in[0];
    const float* pos    = (const float*)d_in[1];
    const float* ea     = (const float*)d_in[2];
    const float* up_w1  = (const float*)d_in[3];
    const float* up_b1  = (const float*)d_in[4];
    const float* up_w2  = (const float*)d_in[5];
    const float* up_b2  = (const float*)d_in[6];
    const float* c1_w   = (const float*)d_in[7];
    const float* c1_b   = (const float*)d_in[8];
    const float* c2_w   = (const float*)d_in[9];
    const float* c2_b   = (const float*)d_in[10];
    const float* c3_w   = (const float*)d_in[11];
    const float* c3_b   = (const float*)d_in[12];
    const float* dw1    = (const float*)d_in[13];
    const float* db1    = (const float*)d_in[14];
    const float* dw2    = (const float*)d_in[15];
    const float* db2    = (const float*)d_in[16];
    const int*   ei     = (const int*)d_in[17];
    const int* row = ei;
    const int* col = ei + EE;

    float *z, *h, *p1, *p2, *p3, *y0, *y1, *y2, *y3, *pp1, *pp2, *pp3, *posacc;
    __nv_bfloat16 *wt1, *wt2, *wt3;
    cudaGetSymbolAddress((void**)&z,      g_z);
    cudaGetSymbolAddress((void**)&h,      g_h);
    cudaGetSymbolAddress((void**)&p1,     g_p1);
    cudaGetSymbolAddress((void**)&p2,     g_p2);
    cudaGetSymbolAddress((void**)&p3,     g_p3);
    cudaGetSymbolAddress((void**)&y0,     g_y0);
    cudaGetSymbolAddress((void**)&y1,     g_y1);
    cudaGetSymbolAddress((void**)&y2,     g_y2);
    cudaGetSymbolAddress((void**)&y3,     g_y3);
    cudaGetSymbolAddress((void**)&pp1,    g_pp1);
    cudaGetSymbolAddress((void**)&pp2,    g_pp2);
    cudaGetSymbolAddress((void**)&pp3,    g_pp3);
    cudaGetSymbolAddress((void**)&posacc, g_posacc);
    cudaGetSymbolAddress((void**)&wt1,    g_wt1);
    cudaGetSymbolAddress((void**)&wt2,    g_wt2);
    cudaGetSymbolAddress((void**)&wt3,    g_wt3);

    const int SM64  = 4 * 128 * (64 + 8) * 2;    // 73728
    const int SM128 = 4 * 128 * (128 + 8) * 2;   // 139264
    cudaFuncSetAttribute((const void*)k_mma<64, 4, 0>,  cudaFuncAttributeMaxDynamicSharedMemorySize, SM64);
    cudaFuncSetAttribute((const void*)k_mma<128, 4, 0>, cudaFuncAttributeMaxDynamicSharedMemorySize, SM128);
    cudaFuncSetAttribute((const void*)k_mma<128, 1, 1>, cudaFuncAttributeMaxDynamicSharedMemorySize, SM128);

    const int GN = (NN + 255) / 256;
    const int GE = (EE + 255) / 256;
    const int GW = (NN + 7) / 8;
    const int GT = (NN + 127) / 128;
    const int GP = (NN * HID + 255) / 256;

    // --- graph setup ---
    k_zero<<<GN, 256>>>();
    k_hist<<<GE, 256>>>(col, ea);
    k_dinv<<<GN, 256>>>();
    k_scan<<<1, 1024>>>();
    k_cursor<<<GN, 256>>>();
    k_scatter<<<GE, 256>>>(row, col, ea);

    // --- weight prep (bf16 hi/lo, transposed) ---
    k_wprep1<<<(4 * 128 * 64 + 255) / 256, 256>>>(c1_w);
    k_wprep2<<<(4 * 128 * 128 + 255) / 256, 256>>>(c2_w);
    k_wprep3<<<(2 * 128 * 128 + 255) / 256, 256>>>(c3_w);

    // --- iteration-invariant pos hops + posacc ---
    k_prop3<<<GN, 256>>>(pp1, pos);
    k_prop3<<<GN, 256>>>(pp2, pp1);
    k_prop3<<<GN, 256>>>(pp3, pp2);
    k_posacc<<<GP, 256>>>(pos, c1_w);

    // --- up MLP -> z0 ---
    k_up<<<(NN + 3) / 4, 256>>>(x, up_w1, up_b1, up_w2, up_b2);

    // --- 21 gnn applications ---
    for (int it = 0; it < 21; it++) {
        // tag1: hops on z (64ch), tensor GEMM (+posacc, relu) -> h
        k_prop64<<<GW, 256>>>(p1, z);
        k_prop64<<<GW, 256>>>(p2, p1);
        k_prop64<<<GW, 256>>>(p3, p2);
        k_mma<64, 4, 0><<<GT, 256, SM64>>>(z, p1, p2, p3, wt1, posacc, c1_b, h, nullptr);

        // tag2: hops on h (128ch), tensor GEMM (relu) -> h
        k_prop128<<<GW, 256>>>(p1, h);
        k_prop128<<<GW, 256>>>(p2, p1);
        k_prop128<<<GW, 256>>>(p3, p2);
        k_mma<128, 4, 0><<<GT, 256, SM128>>>(h, p1, p2, p3, wt2, nullptr, c2_b, h, nullptr);

        // tag3: paired tensor GEMMs first, then 64ch prop chain
        k_mma<128, 1, 1><<<GT, 256, SM128>>>(h, h, h, h, wt3,                 nullptr, nullptr, y0, y1);
        k_mma<128, 1, 1><<<GT, 256, SM128>>>(h, h, h, h, wt3 + 2 * 128 * 128, nullptr, nullptr, y2, y3);
        k_propadd64<<<GW, 256>>>(p1, y3, y2);
        k_propadd64<<<GW, 256>>>(p2, p1, y1);
        k_proplogsm<<<GW, 256>>>(p2, y0, c3_b);
    }

    // --- down MLP + write (out, z_star) ---
    k_down<<<GW, 256>>>((float*)d_out, dw1, db1, dw2, db2);

    (void)in_sizes; (void)n_in; (void)out_size;
}